// round 13
// baseline (speedup 1.0000x reference)
#include <cuda_runtime.h>
#include <cuda_bf16.h>
#include <cstdint>

#define WDIM 256

// ---------------------------------------------------------------------------
// Scratch (device globals)
// ---------------------------------------------------------------------------
__device__ float g_xs[2560000];              // [N,256]
__device__ float g_xt[2560000];
__device__ unsigned short g_x_hi[2560000];   // x bf16 hi/lo [N,256]
__device__ unsigned short g_x_lo[2560000];
__device__ unsigned short g_wp_hi[65536];    // W_post bf16 hi [n,k]
__device__ unsigned short g_wp_lo[65536];
__device__ unsigned short g_wsrc_hi[65536];  // W_src bf16 hi/lo [n,k]
__device__ unsigned short g_wsrc_lo[65536];
__device__ unsigned short g_wtgt_hi[65536];
__device__ unsigned short g_wtgt_lo[65536];
// gate/val weights pre-arranged as m16n8k16 B-fragments (R6-validated layout):
// index = (((c*4 + role)*32 + lane)*32 + slot), role = hl*2+nh
// slot: 0-7 Wg hi [ks*4+r], 8-15 Wg lo, 16-23 Wv hi, 24-31 Wv lo
__device__ unsigned g_wgv_frag[16384];

typedef unsigned long long u64;

__device__ __forceinline__ unsigned sw128(unsigned x) { return x ^ ((x >> 3) & 0x70u); }
__device__ __forceinline__ void cpa16(unsigned dst, const void* src) {
    asm volatile("cp.async.cg.shared.global [%0], [%1], 16;" :: "r"(dst), "l"(src));
}
__device__ __forceinline__ void zfill16(unsigned dst) {
    asm volatile("st.shared.v4.b32 [%0], {%1,%1,%1,%1};" :: "r"(dst), "r"(0u));
}
__device__ __forceinline__ void ldm_x4(unsigned* r, unsigned addr) {
    asm volatile("ldmatrix.sync.aligned.m8n8.x4.shared.b16 {%0,%1,%2,%3}, [%4];"
                 : "=r"(r[0]), "=r"(r[1]), "=r"(r[2]), "=r"(r[3]) : "r"(addr));
}
__device__ __forceinline__ void mma16816(float* d, const unsigned* a,
                                         unsigned b0, unsigned b1) {
    asm volatile(
        "mma.sync.aligned.m16n8k16.row.col.f32.bf16.bf16.f32 "
        "{%0,%1,%2,%3}, {%4,%5,%6,%7}, {%8,%9}, {%0,%1,%2,%3};"
        : "+f"(d[0]), "+f"(d[1]), "+f"(d[2]), "+f"(d[3])
        : "r"(a[0]), "r"(a[1]), "r"(a[2]), "r"(a[3]), "r"(b0), "r"(b1));
}
// pack 2 fp32 -> bf16x2 (hi16 = a1, lo16 = a0)
__device__ __forceinline__ unsigned bf2(float a1, float a0) {
    unsigned d;
    asm("cvt.rn.bf16x2.f32 %0, %1, %2;" : "=r"(d) : "f"(a1), "f"(a0));
    return d;
}

// ---------------------------------------------------------------------------
// Split x into bf16 hi/lo
// ---------------------------------------------------------------------------
extern "C" __global__ void xsplit_kernel(const float* __restrict__ x, int total)
{
    int i = blockIdx.x * blockDim.x + threadIdx.x;
    if (i < total) {
        float v = x[i];
        __nv_bfloat16 h = __float2bfloat16(v);
        float lof = v - __bfloat162float(h);
        __nv_bfloat16 l = __float2bfloat16(lof);
        g_x_hi[i] = *reinterpret_cast<unsigned short*>(&h);
        g_x_lo[i] = *reinterpret_cast<unsigned short*>(&l);
    }
}

// ---------------------------------------------------------------------------
// Weight preprocessing: W_post/W_src/W_tgt hi/lo + Wg/Wv B-fragments (R6)
// ---------------------------------------------------------------------------
extern "C" __global__ void wsplit_kernel(const float* __restrict__ Wp,
                                         const float* __restrict__ Ws,
                                         const float* __restrict__ Wt,
                                         const float* __restrict__ Wg,
                                         const float* __restrict__ Wv)
{
    int i = blockIdx.x * blockDim.x + threadIdx.x;
    if (i < 65536) {
        {
            float v = Wp[i];
            __nv_bfloat16 h = __float2bfloat16(v);
            float lof = v - __bfloat162float(h);
            __nv_bfloat16 l = __float2bfloat16(lof);
            g_wp_hi[i] = *reinterpret_cast<unsigned short*>(&h);
            g_wp_lo[i] = *reinterpret_cast<unsigned short*>(&l);
        }
        {
            float v = Ws[i];
            __nv_bfloat16 h = __float2bfloat16(v);
            float lof = v - __bfloat162float(h);
            __nv_bfloat16 l = __float2bfloat16(lof);
            g_wsrc_hi[i] = *reinterpret_cast<unsigned short*>(&h);
            g_wsrc_lo[i] = *reinterpret_cast<unsigned short*>(&l);
        }
        {
            float v = Wt[i];
            __nv_bfloat16 h = __float2bfloat16(v);
            float lof = v - __bfloat162float(h);
            __nv_bfloat16 l = __float2bfloat16(lof);
            g_wtgt_hi[i] = *reinterpret_cast<unsigned short*>(&h);
            g_wtgt_lo[i] = *reinterpret_cast<unsigned short*>(&l);
        }
    }
    if (i < 16384) {
        // R6-validated fragment layout (must mirror P2 consumption exactly)
        int c    = i >> 12;
        int role = (i >> 10) & 3;        // hl*2 + nh
        int hl   = role >> 1, nh = role & 1;
        int lane = (i >> 5) & 31;
        int slot = i & 31;
        int m  = slot >> 3;              // 0 gh, 1 gl, 2 vh, 3 vl
        int r8 = slot & 7;
        int ks = r8 >> 2;
        int r  = r8 & 3;
        int j  = r >> 1, p = r & 1;
        int h = c * 2 + hl;
        int f = nh * 16 + j * 8 + (lane >> 2);
        int d = ks * 16 + p * 8 + 2 * (lane & 3);
        const float* Wm = (m < 2) ? Wg : Wv;
        float v0 = Wm[(size_t)h * 1024 + f * 32 + d];
        float v1 = Wm[(size_t)h * 1024 + f * 32 + d + 1];
        if ((m & 1) == 0) {
            g_wgv_frag[i] = bf2(v1, v0);
        } else {
            float h0 = __bfloat162float(__float2bfloat16(v0));
            float h1 = __bfloat162float(__float2bfloat16(v1));
            g_wgv_frag[i] = bf2(v1 - h1, v0 - h0);
        }
    }
}

// ---------------------------------------------------------------------------
// K1: HMMA node GEMM (R10, unchanged). Block = 128 nodes x 256 outs.
// ---------------------------------------------------------------------------
extern "C" __global__ void __launch_bounds__(512, 1)
hmma_node_kernel(int N)
{
    extern __shared__ char smc[];
    unsigned sb = (unsigned)__cvta_generic_to_shared(smc);
    const unsigned A_HI = sb, A_LO = sb + 16384u, B_HI = sb + 32768u, B_LO = sb + 65536u;
    const int t = threadIdx.x, lane = t & 31, wid = t >> 5;
    const int wm = wid & 3, wn = wid >> 2;
    const int m0 = wm * 32, n0 = wn * 64;
    const int nb = blockIdx.x * 128;
    const unsigned short* Wh = blockIdx.y ? g_wtgt_hi : g_wsrc_hi;
    const unsigned short* Wl = blockIdx.y ? g_wtgt_lo : g_wsrc_lo;
    float* og = blockIdx.y ? g_xt : g_xs;

    float acc[2][8][4];
#pragma unroll
    for (int mt = 0; mt < 2; mt++)
#pragma unroll
        for (int nn = 0; nn < 8; nn++)
#pragma unroll
            for (int q = 0; q < 4; q++) acc[mt][nn][q] = 0.f;

#pragma unroll 1
    for (int c = 0; c < 4; c++) {
        __syncthreads();
#pragma unroll
        for (int i = 0; i < 2; i++) {
            int u = t + 512 * i;
            int r = u >> 3, q = u & 7;
            unsigned off = sw128((unsigned)(r * 128 + q * 16));
            int row = nb + r;
            if (row < N) {
                cpa16(A_HI + off, g_x_hi + (size_t)row * 256 + c * 64 + q * 8);
                cpa16(A_LO + off, g_x_lo + (size_t)row * 256 + c * 64 + q * 8);
            } else {
                zfill16(A_HI + off);
                zfill16(A_LO + off);
            }
        }
#pragma unroll
        for (int i = 0; i < 4; i++) {
            int u = t + 512 * i;
            int n = u >> 3, q = u & 7;
            unsigned off = sw128((unsigned)(n * 128 + q * 16));
            cpa16(B_HI + off, Wh + (size_t)n * 256 + c * 64 + q * 8);
            cpa16(B_LO + off, Wl + (size_t)n * 256 + c * 64 + q * 8);
        }
        asm volatile("cp.async.commit_group;" ::: "memory");
        asm volatile("cp.async.wait_group 0;" ::: "memory");
        __syncthreads();

#pragma unroll
        for (int ks = 0; ks < 4; ks++) {
            unsigned ah[2][4], al[2][4];
#pragma unroll
            for (int mt = 0; mt < 2; mt++) {
                unsigned off = sw128((unsigned)((m0 + mt * 16 + (lane & 15)) * 128
                                                + ks * 32 + (lane >> 4) * 16));
                ldm_x4(ah[mt], A_HI + off);
                ldm_x4(al[mt], A_LO + off);
            }
#pragma unroll
            for (int nt = 0; nt < 4; nt++) {
                unsigned off = sw128((unsigned)((n0 + nt * 16 + (lane & 7)
                                                 + ((lane >> 4) & 1) * 8) * 128
                                                + ks * 32 + ((lane >> 3) & 1) * 16));
                unsigned bh[4], bl[4];
                ldm_x4(bh, B_HI + off);
                ldm_x4(bl, B_LO + off);
#pragma unroll
                for (int j = 0; j < 2; j++) {
                    int nn = nt * 2 + j;
#pragma unroll
                    for (int mt = 0; mt < 2; mt++) {
                        mma16816(acc[mt][nn], ah[mt], bh[2 * j], bh[2 * j + 1]);
                        mma16816(acc[mt][nn], ah[mt], bl[2 * j], bl[2 * j + 1]);
                        mma16816(acc[mt][nn], al[mt], bh[2 * j], bh[2 * j + 1]);
                    }
                }
            }
        }
    }

#pragma unroll
    for (int mt = 0; mt < 2; mt++) {
        int r0 = nb + m0 + mt * 16 + (lane >> 2);
        int r1 = r0 + 8;
#pragma unroll
        for (int nn = 0; nn < 8; nn++) {
            int col = n0 + nn * 8 + (lane & 3) * 2;
            if (r0 < N) {
                og[(size_t)r0 * WDIM + col]     = acc[mt][nn][0];
                og[(size_t)r0 * WDIM + col + 1] = acc[mt][nn][1];
            }
            if (r1 < N) {
                og[(size_t)r1 * WDIM + col]     = acc[mt][nn][2];
                og[(size_t)r1 * WDIM + col + 1] = acc[mt][nn][3];
            }
        }
    }
}

// ---------------------------------------------------------------------------
// K2 (fused), R13 = R12 M-split + WGV via register-direct LDG fragments.
// Each CTA: 32 edges x 256 out-cols, 256 threads (8 warps), 2 CTAs/SM.
// smem: tgt@0(pad 1024) | XNH@1024(4K) XNL@5120 GINH@9216 GINL@13312
//  | ACTH@17408(4K) ACTL@21504 | WPH@25600(32K) WPL@58368 -> 91136 B
// ---------------------------------------------------------------------------
#define XNH_O  1024u
#define XNL_O  5120u
#define GINH_O 9216u
#define GINL_O 13312u
#define ACTH_O 17408u
#define ACTL_O 21504u
#define WPH_O  25600u
#define WPL_O  58368u

extern "C" __global__ void __launch_bounds__(256, 2)
fused_edge_kernel(const int* __restrict__ eidx, const int* __restrict__ eattr,
                  const float* __restrict__ emb, float* __restrict__ out, int E)
{
    extern __shared__ char smc[];
    unsigned sb = (unsigned)__cvta_generic_to_shared(smc);
    int* tgt_s = reinterpret_cast<int*>(smc);
    const int t = threadIdx.x, lane = t & 31, wid = t >> 5;
    const int eb = blockIdx.x * 32;

    if (t < 32) {
        int e = eb + t;
        tgt_s[t] = (e < E) ? __ldg(eidx + E + e) : -1;
    }
    __syncthreads();

    // P3 warp grid: 1m x 8n, warp tile 32x32 over (32 edges x 256 cols)
    const int n0 = wid * 32;
    float acc[2][4][4];
#pragma unroll
    for (int mt = 0; mt < 2; mt++)
#pragma unroll
        for (int nn = 0; nn < 4; nn++)
#pragma unroll
            for (int q = 0; q < 4; q++) acc[mt][nn][q] = 0.f;

    const int e_l = t >> 3, sub = t & 7;   // 32 edges x 8 subs
    const int e = eb + e_l;
    // P2 warp mapping: 8 warps = eg(2) x hl(2) x nh(2)
    const int eg = wid >> 2, hl = (wid >> 1) & 1, nh = wid & 1;
    const int role = wid & 3;

    // ---- stage WP chunk (hi/lo 32KB each) ----
    auto stage = [&](int cc) {
#pragma unroll
        for (int i = 0; i < 8; i++) {
            int u = t + 256 * i;
            int n = u >> 3, q = u & 7;
            unsigned off = sw128((unsigned)(n * 128 + q * 16));
            cpa16(sb + WPH_O + off, g_wp_hi + (size_t)n * 256 + cc * 64 + q * 8);
            cpa16(sb + WPL_O + off, g_wp_lo + (size_t)n * 256 + cc * 64 + q * 8);
        }
        asm volatile("cp.async.commit_group;" ::: "memory");
    };

#pragma unroll 1
    for (int c = 0; c < 4; c++) {
        stage(c);   // after S3(c-1): WP buffer free

        // ---- P1: xn/gin for this chunk's 2 heads ----
        {
            unsigned soff = sw128((unsigned)(e_l * 128 + sub * 16));
            if (e < E) {
                int s  = __ldg(eidx + e);
                int tg = tgt_s[e_l];
                const float4* ps = reinterpret_cast<const float4*>(
                    g_xs + (size_t)s * WDIM + c * 64 + sub * 8);
                const float4* pt = reinterpret_cast<const float4*>(
                    g_xt + (size_t)tg * WDIM + c * 64 + sub * 8);
                float xx[8];
                float4 a0 = ps[0], a1 = ps[1], b0 = pt[0], b1 = pt[1];
                xx[0] = a0.x + b0.x; xx[1] = a0.y + b0.y; xx[2] = a0.z + b0.z; xx[3] = a0.w + b0.w;
                xx[4] = a1.x + b1.x; xx[5] = a1.y + b1.y; xx[6] = a1.z + b1.z; xx[7] = a1.w + b1.w;
                float sum = 0.f, sq = 0.f;
#pragma unroll
                for (int i = 0; i < 8; i++) { sum += xx[i]; sq += xx[i] * xx[i]; }
                sum += __shfl_xor_sync(0xFFFFFFFFu, sum, 1);
                sq  += __shfl_xor_sync(0xFFFFFFFFu, sq, 1);
                sum += __shfl_xor_sync(0xFFFFFFFFu, sum, 2);
                sq  += __shfl_xor_sync(0xFFFFFFFFu, sq, 2);
                float mu = sum * (1.f / 32.f);
                float var = sq * (1.f / 32.f) - mu * mu;
                float rstd = rsqrtf(var + 1e-5f);

                float bag[8];
#pragma unroll
                for (int i = 0; i < 8; i++) bag[i] = 0.f;
                float cnt = 0.f;
#pragma unroll
                for (int b = 0; b < 3; b++) {
                    int a = __ldg(eattr + (size_t)e * 3 + b);
                    if (a != 0) {
                        cnt += 1.f;
                        const float4* pe = reinterpret_cast<const float4*>(
                            emb + (size_t)a * WDIM + c * 64 + sub * 8);
                        float4 e0 = __ldg(pe), e1 = __ldg(pe + 1);
                        bag[0] += e0.x; bag[1] += e0.y; bag[2] += e0.z; bag[3] += e0.w;
                        bag[4] += e1.x; bag[5] += e1.y; bag[6] += e1.z; bag[7] += e1.w;
                    }
                }
                float inv = 1.f / fmaxf(cnt, 1.f);
                float xn[8], gn[8];
#pragma unroll
                for (int i = 0; i < 8; i++) {
                    xn[i] = (xx[i] - mu) * rstd;
                    gn[i] = xn[i] + bag[i] * inv;
                }
                unsigned xh[4], xl[4], gh[4], gl[4];
#pragma unroll
                for (int p = 0; p < 4; p++) {
                    unsigned hp = bf2(xn[2 * p + 1], xn[2 * p]);
                    float h0 = __uint_as_float(hp << 16);
                    float h1 = __uint_as_float(hp & 0xFFFF0000u);
                    xh[p] = hp;
                    xl[p] = bf2(xn[2 * p + 1] - h1, xn[2 * p] - h0);
                    hp = bf2(gn[2 * p + 1], gn[2 * p]);
                    h0 = __uint_as_float(hp << 16);
                    h1 = __uint_as_float(hp & 0xFFFF0000u);
                    gh[p] = hp;
                    gl[p] = bf2(gn[2 * p + 1] - h1, gn[2 * p] - h0);
                }
                asm volatile("st.shared.v4.b32 [%0], {%1,%2,%3,%4};" ::
                             "r"(sb + XNH_O + soff), "r"(xh[0]), "r"(xh[1]), "r"(xh[2]), "r"(xh[3]));
                asm volatile("st.shared.v4.b32 [%0], {%1,%2,%3,%4};" ::
                             "r"(sb + XNL_O + soff), "r"(xl[0]), "r"(xl[1]), "r"(xl[2]), "r"(xl[3]));
                asm volatile("st.shared.v4.b32 [%0], {%1,%2,%3,%4};" ::
                             "r"(sb + GINH_O + soff), "r"(gh[0]), "r"(gh[1]), "r"(gh[2]), "r"(gh[3]));
                asm volatile("st.shared.v4.b32 [%0], {%1,%2,%3,%4};" ::
                             "r"(sb + GINL_O + soff), "r"(gl[0]), "r"(gl[1]), "r"(gl[2]), "r"(gl[3]));
            } else {
                asm volatile("st.shared.v4.b32 [%0], {%1,%1,%1,%1};" :: "r"(sb + XNH_O + soff), "r"(0u));
                asm volatile("st.shared.v4.b32 [%0], {%1,%1,%1,%1};" :: "r"(sb + XNL_O + soff), "r"(0u));
                asm volatile("st.shared.v4.b32 [%0], {%1,%1,%1,%1};" :: "r"(sb + GINH_O + soff), "r"(0u));
                asm volatile("st.shared.v4.b32 [%0], {%1,%1,%1,%1};" :: "r"(sb + GINL_O + soff), "r"(0u));
            }
        }
        asm volatile("cp.async.wait_group 0;" ::: "memory");
        __syncthreads();   // S1: xn/gin + WP(c) visible

        // ---- P2: gate/val HMMA, B-fragments direct from global (R6 layout) --
        {
            unsigned bfr[32];
            const uint4* pw = reinterpret_cast<const uint4*>(
                g_wgv_frag + ((size_t)((c * 4 + role) * 32 + lane) * 32));
#pragma unroll
            for (int i = 0; i < 8; i++) {
                uint4 q = __ldg(pw + i);
                bfr[i * 4] = q.x; bfr[i * 4 + 1] = q.y;
                bfr[i * 4 + 2] = q.z; bfr[i * 4 + 3] = q.w;
            }
            unsigned agh[2][4], agl[2][4], axh[2][4], axl[2][4];
            unsigned arow = (unsigned)((eg * 16 + (lane & 15)) * 128 + hl * 64 + (lane >> 4) * 16);
#pragma unroll
            for (int ks = 0; ks < 2; ks++) {
                unsigned off = sw128(arow + ks * 32);
                ldm_x4(agh[ks], sb + GINH_O + off);
                ldm_x4(agl[ks], sb + GINL_O + off);
                ldm_x4(axh[ks], sb + XNH_O + off);
                ldm_x4(axl[ks], sb + XNL_O + off);
            }
            float gacc[2][4], vacc[2][4];
#pragma unroll
            for (int j = 0; j < 2; j++)
#pragma unroll
                for (int q = 0; q < 4; q++) { gacc[j][q] = 0.f; vacc[j][q] = 0.f; }
#pragma unroll
            for (int ks = 0; ks < 2; ks++)
#pragma unroll
                for (int j = 0; j < 2; j++) {
                    mma16816(gacc[j], agh[ks], bfr[ks * 4 + 2 * j],      bfr[ks * 4 + 2 * j + 1]);
                    mma16816(gacc[j], agh[ks], bfr[8 + ks * 4 + 2 * j],  bfr[8 + ks * 4 + 2 * j + 1]);
                    mma16816(gacc[j], agl[ks], bfr[ks * 4 + 2 * j],      bfr[ks * 4 + 2 * j + 1]);
                    mma16816(vacc[j], axh[ks], bfr[16 + ks * 4 + 2 * j], bfr[16 + ks * 4 + 2 * j + 1]);
                    mma16816(vacc[j], axh[ks], bfr[24 + ks * 4 + 2 * j], bfr[24 + ks * 4 + 2 * j + 1]);
                    mma16816(vacc[j], axl[ks], bfr[16 + ks * 4 + 2 * j], bfr[16 + ks * 4 + 2 * j + 1]);
                }
#pragma unroll
            for (int j = 0; j < 2; j++)
#pragma unroll
                for (int half = 0; half < 2; half++) {
                    float a0 = fmaxf(gacc[j][half * 2], 0.f) * vacc[j][half * 2];
                    float a1 = fmaxf(gacc[j][half * 2 + 1], 0.f) * vacc[j][half * 2 + 1];
                    int row = eg * 16 + (lane >> 2) + half * 8;
                    int col = hl * 32 + nh * 16 + j * 8 + (lane & 3) * 2;
                    unsigned off = sw128((unsigned)(row * 128 + col * 2));
                    unsigned hp = bf2(a1, a0);
                    float h0 = __uint_as_float(hp << 16);
                    float h1 = __uint_as_float(hp & 0xFFFF0000u);
                    unsigned lp = bf2(a1 - h1, a0 - h0);
                    asm volatile("st.shared.b32 [%0], %1;" :: "r"(sb + ACTH_O + off), "r"(hp));
                    asm volatile("st.shared.b32 [%0], %1;" :: "r"(sb + ACTL_O + off), "r"(lp));
                }
        }
        __syncthreads();   // S2: act visible

        // ---- P3: W_post chunk mainloop (warp tile 32x32, m0 = 0) ----
        {
#pragma unroll
            for (int ks = 0; ks < 4; ks++) {
                unsigned ah[2][4], al[2][4];
#pragma unroll
                for (int mt = 0; mt < 2; mt++) {
                    unsigned off = sw128((unsigned)((mt * 16 + (lane & 15)) * 128
                                                    + ks * 32 + (lane >> 4) * 16));
                    ldm_x4(ah[mt], sb + ACTH_O + off);
                    ldm_x4(al[mt], sb + ACTL_O + off);
                }
#pragma unroll
                for (int nt = 0; nt < 2; nt++) {
                    unsigned off = sw128((unsigned)((n0 + nt * 16 + (lane & 7)
                                                     + ((lane >> 4) & 1) * 8) * 128
                                                    + ks * 32 + ((lane >> 3) & 1) * 16));
                    unsigned bh[4], bl[4];
                    ldm_x4(bh, sb + WPH_O + off);
                    ldm_x4(bl, sb + WPL_O + off);
#pragma unroll
                    for (int j = 0; j < 2; j++) {
                        int nn = nt * 2 + j;
#pragma unroll
                        for (int mt = 0; mt < 2; mt++) {
                            mma16816(acc[mt][nn], ah[mt], bh[2 * j], bh[2 * j + 1]);
                            mma16816(acc[mt][nn], ah[mt], bl[2 * j], bl[2 * j + 1]);
                            mma16816(acc[mt][nn], al[mt], bh[2 * j], bh[2 * j + 1]);
                        }
                    }
                }
            }
        }
        __syncthreads();   // S3: P3 reads done; next chunk may restage WP/act
    }

    // ---- epilogue: scatter ----
#pragma unroll
    for (int mt = 0; mt < 2; mt++) {
        int r0 = mt * 16 + (lane >> 2);
        int r1 = r0 + 8;
        int tg0 = tgt_s[r0], tg1 = tgt_s[r1];
        float* p0 = out + (size_t)(tg0 < 0 ? 0 : tg0) * WDIM;
        float* p1 = out + (size_t)(tg1 < 0 ? 0 : tg1) * WDIM;
#pragma unroll
        for (int nn = 0; nn < 4; nn++) {
            int col = n0 + nn * 8 + (lane & 3) * 2;
            if (tg0 >= 0)
                asm volatile("red.global.add.v2.f32 [%0], {%1,%2};" ::
                             "l"(p0 + col), "f"(acc[mt][nn][0]), "f"(acc[mt][nn][1]) : "memory");
            if (tg1 >= 0)
                asm volatile("red.global.add.v2.f32 [%0], {%1,%2};" ::
                             "l"(p1 + col), "f"(acc[mt][nn][2]), "f"(acc[mt][nn][3]) : "memory");
        }
    }
}

// ---------------------------------------------------------------------------
// K3: out[n,j] *= deg[n]^deg_param[j]
// ---------------------------------------------------------------------------
extern "C" __global__ void scale_kernel(float* __restrict__ out,
                                        const float* __restrict__ deg,
                                        const float* __restrict__ dp, int N)
{
    int idx = blockIdx.x * blockDim.x + threadIdx.x;
    if (idx < N * WDIM) {
        int n = idx >> 8, j = idx & 255;
        out[idx] *= __powf(__ldg(deg + n), __ldg(dp + j));
    }
}

// ---------------------------------------------------------------------------
extern "C" void kernel_launch(void* const* d_in, const int* in_sizes, int n_in,
                              void* d_out, int out_size)
{
    const float* x    = (const float*)d_in[0];
    const float* deg  = (const float*)d_in[1];
    const int*   eidx = (const int*)d_in[2];
    const int*   eattr= (const int*)d_in[3];
    const float* Wsrc = (const float*)d_in[4];
    const float* Wtgt = (const float*)d_in[5];
    const float* emb  = (const float*)d_in[6];
    const float* Wg   = (const float*)d_in[7];
    const float* Wv   = (const float*)d_in[8];
    const float* Wp   = (const float*)d_in[9];
    const float* dp   = (const float*)d_in[10];
    float* out = (float*)d_out;

    int N = in_sizes[0] / WDIM;
    int E = in_sizes[2] / 2;
    int xtotal = in_sizes[0];

    const int NODE_SMEM  = 98304;
    const int FUSED_SMEM = 91136;

    cudaFuncSetAttribute(hmma_node_kernel,
                         cudaFuncAttributeMaxDynamicSharedMemorySize, NODE_SMEM);
    cudaFuncSetAttribute(fused_edge_kernel,
                         cudaFuncAttributeMaxDynamicSharedMemorySize, FUSED_SMEM);

    cudaMemsetAsync(d_out, 0, (size_t)out_size * sizeof(float));

    xsplit_kernel<<<(xtotal + 511) / 512, 512>>>(x, xtotal);
    wsplit_kernel<<<64, 1024>>>(Wp, Wsrc, Wtgt, Wg, Wv);
    dim3 ng((N + 127) / 128, 2);
    hmma_node_kernel<<<ng, 512, NODE_SMEM>>>(N);
    fused_edge_kernel<<<(E + 31) / 32, 256, FUSED_SMEM>>>(eidx, eattr, emb, out, E);
    scale_kernel<<<((size_t)N * WDIM + 511) / 512, 512>>>(out, deg, dp, N);
}

// round 14
// speedup vs baseline: 1.3234x; 1.3234x over previous
#include <cuda_runtime.h>
#include <cuda_bf16.h>
#include <cstdint>

#define WDIM 256

// ---------------------------------------------------------------------------
// Scratch (device globals)
// ---------------------------------------------------------------------------
__device__ float g_xs[2560000];              // [N,256]
__device__ float g_xt[2560000];
__device__ unsigned short g_x_hi[2560000];   // x bf16 hi/lo [N,256]
__device__ unsigned short g_x_lo[2560000];
__device__ unsigned short g_wp_hi[65536];    // W_post bf16 hi [n,k]
__device__ unsigned short g_wp_lo[65536];
__device__ unsigned short g_wsrc_hi[65536];  // W_src bf16 hi/lo [n,k]
__device__ unsigned short g_wsrc_lo[65536];
__device__ unsigned short g_wtgt_hi[65536];
__device__ unsigned short g_wtgt_lo[65536];
// gate/val weights as m16n8k16 B-fragments, LANE-COALESCED layout:
// u32 index = ((((c*4 + role)*8 + i)*32 + lane)*4 + q), slot = i*4 + q
// slot semantics (R6-validated): 0-7 Wg hi [ks*4+r], 8-15 Wg lo,
//                                16-23 Wv hi, 24-31 Wv lo
__device__ unsigned g_wgv_frag[16384];

typedef unsigned long long u64;

__device__ __forceinline__ unsigned sw128(unsigned x) { return x ^ ((x >> 3) & 0x70u); }
__device__ __forceinline__ void cpa16(unsigned dst, const void* src) {
    asm volatile("cp.async.cg.shared.global [%0], [%1], 16;" :: "r"(dst), "l"(src));
}
__device__ __forceinline__ void zfill16(unsigned dst) {
    asm volatile("st.shared.v4.b32 [%0], {%1,%1,%1,%1};" :: "r"(dst), "r"(0u));
}
__device__ __forceinline__ void ldm_x4(unsigned* r, unsigned addr) {
    asm volatile("ldmatrix.sync.aligned.m8n8.x4.shared.b16 {%0,%1,%2,%3}, [%4];"
                 : "=r"(r[0]), "=r"(r[1]), "=r"(r[2]), "=r"(r[3]) : "r"(addr));
}
__device__ __forceinline__ void mma16816(float* d, const unsigned* a,
                                         unsigned b0, unsigned b1) {
    asm volatile(
        "mma.sync.aligned.m16n8k16.row.col.f32.bf16.bf16.f32 "
        "{%0,%1,%2,%3}, {%4,%5,%6,%7}, {%8,%9}, {%0,%1,%2,%3};"
        : "+f"(d[0]), "+f"(d[1]), "+f"(d[2]), "+f"(d[3])
        : "r"(a[0]), "r"(a[1]), "r"(a[2]), "r"(a[3]), "r"(b0), "r"(b1));
}
// pack 2 fp32 -> bf16x2 (hi16 = a1, lo16 = a0)
__device__ __forceinline__ unsigned bf2(float a1, float a0) {
    unsigned d;
    asm("cvt.rn.bf16x2.f32 %0, %1, %2;" : "=r"(d) : "f"(a1), "f"(a0));
    return d;
}

// ---------------------------------------------------------------------------
// Split x into bf16 hi/lo
// ---------------------------------------------------------------------------
extern "C" __global__ void xsplit_kernel(const float* __restrict__ x, int total)
{
    int i = blockIdx.x * blockDim.x + threadIdx.x;
    if (i < total) {
        float v = x[i];
        __nv_bfloat16 h = __float2bfloat16(v);
        float lof = v - __bfloat162float(h);
        __nv_bfloat16 l = __float2bfloat16(lof);
        g_x_hi[i] = *reinterpret_cast<unsigned short*>(&h);
        g_x_lo[i] = *reinterpret_cast<unsigned short*>(&l);
    }
}

// ---------------------------------------------------------------------------
// Weight preprocessing: W_post/W_src/W_tgt hi/lo + Wg/Wv coalesced B-fragments
// ---------------------------------------------------------------------------
extern "C" __global__ void wsplit_kernel(const float* __restrict__ Wp,
                                         const float* __restrict__ Ws,
                                         const float* __restrict__ Wt,
                                         const float* __restrict__ Wg,
                                         const float* __restrict__ Wv)
{
    int m = blockIdx.x * blockDim.x + threadIdx.x;
    if (m < 65536) {
        {
            float v = Wp[m];
            __nv_bfloat16 h = __float2bfloat16(v);
            float lof = v - __bfloat162float(h);
            __nv_bfloat16 l = __float2bfloat16(lof);
            g_wp_hi[m] = *reinterpret_cast<unsigned short*>(&h);
            g_wp_lo[m] = *reinterpret_cast<unsigned short*>(&l);
        }
        {
            float v = Ws[m];
            __nv_bfloat16 h = __float2bfloat16(v);
            float lof = v - __bfloat162float(h);
            __nv_bfloat16 l = __float2bfloat16(lof);
            g_wsrc_hi[m] = *reinterpret_cast<unsigned short*>(&h);
            g_wsrc_lo[m] = *reinterpret_cast<unsigned short*>(&l);
        }
        {
            float v = Wt[m];
            __nv_bfloat16 h = __float2bfloat16(v);
            float lof = v - __bfloat162float(h);
            __nv_bfloat16 l = __float2bfloat16(lof);
            g_wtgt_hi[m] = *reinterpret_cast<unsigned short*>(&h);
            g_wtgt_lo[m] = *reinterpret_cast<unsigned short*>(&l);
        }
    }
    if (m < 16384) {
        // lane-coalesced fragment layout; slot semantics identical to R6
        int q    = m & 3;
        int lane = (m >> 2) & 31;
        int i    = (m >> 7) & 7;
        int role = (m >> 10) & 3;        // hl*2 + nh
        int c    = m >> 12;
        int slot = i * 4 + q;
        int hl   = role >> 1, nh = role & 1;
        int mt   = slot >> 3;            // 0 gh, 1 gl, 2 vh, 3 vl
        int r8 = slot & 7;
        int ks = r8 >> 2;
        int r  = r8 & 3;
        int j  = r >> 1, p = r & 1;
        int h = c * 2 + hl;
        int f = nh * 16 + j * 8 + (lane >> 2);
        int d = ks * 16 + p * 8 + 2 * (lane & 3);
        const float* Wm = (mt < 2) ? Wg : Wv;
        float v0 = Wm[(size_t)h * 1024 + f * 32 + d];
        float v1 = Wm[(size_t)h * 1024 + f * 32 + d + 1];
        if ((mt & 1) == 0) {
            g_wgv_frag[m] = bf2(v1, v0);
        } else {
            float h0 = __bfloat162float(__float2bfloat16(v0));
            float h1 = __bfloat162float(__float2bfloat16(v1));
            g_wgv_frag[m] = bf2(v1 - h1, v0 - h0);
        }
    }
}

// ---------------------------------------------------------------------------
// K1: HMMA node GEMM (R10, unchanged). Block = 128 nodes x 256 outs.
// ---------------------------------------------------------------------------
extern "C" __global__ void __launch_bounds__(512, 1)
hmma_node_kernel(int N)
{
    extern __shared__ char smc[];
    unsigned sb = (unsigned)__cvta_generic_to_shared(smc);
    const unsigned A_HI = sb, A_LO = sb + 16384u, B_HI = sb + 32768u, B_LO = sb + 65536u;
    const int t = threadIdx.x, lane = t & 31, wid = t >> 5;
    const int wm = wid & 3, wn = wid >> 2;
    const int m0 = wm * 32, n0 = wn * 64;
    const int nb = blockIdx.x * 128;
    const unsigned short* Wh = blockIdx.y ? g_wtgt_hi : g_wsrc_hi;
    const unsigned short* Wl = blockIdx.y ? g_wtgt_lo : g_wsrc_lo;
    float* og = blockIdx.y ? g_xt : g_xs;

    float acc[2][8][4];
#pragma unroll
    for (int mt = 0; mt < 2; mt++)
#pragma unroll
        for (int nn = 0; nn < 8; nn++)
#pragma unroll
            for (int q = 0; q < 4; q++) acc[mt][nn][q] = 0.f;

#pragma unroll 1
    for (int c = 0; c < 4; c++) {
        __syncthreads();
#pragma unroll
        for (int i = 0; i < 2; i++) {
            int u = t + 512 * i;
            int r = u >> 3, q = u & 7;
            unsigned off = sw128((unsigned)(r * 128 + q * 16));
            int row = nb + r;
            if (row < N) {
                cpa16(A_HI + off, g_x_hi + (size_t)row * 256 + c * 64 + q * 8);
                cpa16(A_LO + off, g_x_lo + (size_t)row * 256 + c * 64 + q * 8);
            } else {
                zfill16(A_HI + off);
                zfill16(A_LO + off);
            }
        }
#pragma unroll
        for (int i = 0; i < 4; i++) {
            int u = t + 512 * i;
            int n = u >> 3, q = u & 7;
            unsigned off = sw128((unsigned)(n * 128 + q * 16));
            cpa16(B_HI + off, Wh + (size_t)n * 256 + c * 64 + q * 8);
            cpa16(B_LO + off, Wl + (size_t)n * 256 + c * 64 + q * 8);
        }
        asm volatile("cp.async.commit_group;" ::: "memory");
        asm volatile("cp.async.wait_group 0;" ::: "memory");
        __syncthreads();

#pragma unroll
        for (int ks = 0; ks < 4; ks++) {
            unsigned ah[2][4], al[2][4];
#pragma unroll
            for (int mt = 0; mt < 2; mt++) {
                unsigned off = sw128((unsigned)((m0 + mt * 16 + (lane & 15)) * 128
                                                + ks * 32 + (lane >> 4) * 16));
                ldm_x4(ah[mt], A_HI + off);
                ldm_x4(al[mt], A_LO + off);
            }
#pragma unroll
            for (int nt = 0; nt < 4; nt++) {
                unsigned off = sw128((unsigned)((n0 + nt * 16 + (lane & 7)
                                                 + ((lane >> 4) & 1) * 8) * 128
                                                + ks * 32 + ((lane >> 3) & 1) * 16));
                unsigned bh[4], bl[4];
                ldm_x4(bh, B_HI + off);
                ldm_x4(bl, B_LO + off);
#pragma unroll
                for (int j = 0; j < 2; j++) {
                    int nn = nt * 2 + j;
#pragma unroll
                    for (int mt = 0; mt < 2; mt++) {
                        mma16816(acc[mt][nn], ah[mt], bh[2 * j], bh[2 * j + 1]);
                        mma16816(acc[mt][nn], ah[mt], bl[2 * j], bl[2 * j + 1]);
                        mma16816(acc[mt][nn], al[mt], bh[2 * j], bh[2 * j + 1]);
                    }
                }
            }
        }
    }

#pragma unroll
    for (int mt = 0; mt < 2; mt++) {
        int r0 = nb + m0 + mt * 16 + (lane >> 2);
        int r1 = r0 + 8;
#pragma unroll
        for (int nn = 0; nn < 8; nn++) {
            int col = n0 + nn * 8 + (lane & 3) * 2;
            if (r0 < N) {
                og[(size_t)r0 * WDIM + col]     = acc[mt][nn][0];
                og[(size_t)r0 * WDIM + col + 1] = acc[mt][nn][1];
            }
            if (r1 < N) {
                og[(size_t)r1 * WDIM + col]     = acc[mt][nn][2];
                og[(size_t)r1 * WDIM + col + 1] = acc[mt][nn][3];
            }
        }
    }
}

// ---------------------------------------------------------------------------
// K2 (fused), R14 = R12 M-split + WGV coalesced LDG fragments.
// Each CTA: 32 edges x 256 out-cols, 256 threads (8 warps), 2 CTAs/SM.
// smem: tgt@0(pad 1024) | XNH@1024(4K) XNL@5120 GINH@9216 GINL@13312
//  | ACTH@17408(4K) ACTL@21504 | WPH@25600(32K) WPL@58368 -> 91136 B
// ---------------------------------------------------------------------------
#define XNH_O  1024u
#define XNL_O  5120u
#define GINH_O 9216u
#define GINL_O 13312u
#define ACTH_O 17408u
#define ACTL_O 21504u
#define WPH_O  25600u
#define WPL_O  58368u

extern "C" __global__ void __launch_bounds__(256, 2)
fused_edge_kernel(const int* __restrict__ eidx, const int* __restrict__ eattr,
                  const float* __restrict__ emb, float* __restrict__ out, int E)
{
    extern __shared__ char smc[];
    unsigned sb = (unsigned)__cvta_generic_to_shared(smc);
    int* tgt_s = reinterpret_cast<int*>(smc);
    const int t = threadIdx.x, lane = t & 31, wid = t >> 5;
    const int eb = blockIdx.x * 32;

    if (t < 32) {
        int e = eb + t;
        tgt_s[t] = (e < E) ? __ldg(eidx + E + e) : -1;
    }
    __syncthreads();

    // P3 warp grid: 1m x 8n, warp tile 32x32 over (32 edges x 256 cols)
    const int n0 = wid * 32;
    float acc[2][4][4];
#pragma unroll
    for (int mt = 0; mt < 2; mt++)
#pragma unroll
        for (int nn = 0; nn < 4; nn++)
#pragma unroll
            for (int q = 0; q < 4; q++) acc[mt][nn][q] = 0.f;

    const int e_l = t >> 3, sub = t & 7;   // 32 edges x 8 subs
    const int e = eb + e_l;
    // P2 warp mapping: 8 warps = eg(2) x hl(2) x nh(2)
    const int eg = wid >> 2, hl = (wid >> 1) & 1, nh = wid & 1;
    const int role = wid & 3;

    // ---- stage WP chunk (hi/lo 32KB each) ----
    auto stage = [&](int cc) {
#pragma unroll
        for (int i = 0; i < 8; i++) {
            int u = t + 256 * i;
            int n = u >> 3, q = u & 7;
            unsigned off = sw128((unsigned)(n * 128 + q * 16));
            cpa16(sb + WPH_O + off, g_wp_hi + (size_t)n * 256 + cc * 64 + q * 8);
            cpa16(sb + WPL_O + off, g_wp_lo + (size_t)n * 256 + cc * 64 + q * 8);
        }
        asm volatile("cp.async.commit_group;" ::: "memory");
    };

#pragma unroll 1
    for (int c = 0; c < 4; c++) {
        stage(c);   // after S3(c-1): WP buffer free

        // ---- P1: xn/gin for this chunk's 2 heads ----
        {
            unsigned soff = sw128((unsigned)(e_l * 128 + sub * 16));
            if (e < E) {
                int s  = __ldg(eidx + e);
                int tg = tgt_s[e_l];
                const float4* ps = reinterpret_cast<const float4*>(
                    g_xs + (size_t)s * WDIM + c * 64 + sub * 8);
                const float4* pt = reinterpret_cast<const float4*>(
                    g_xt + (size_t)tg * WDIM + c * 64 + sub * 8);
                float xx[8];
                float4 a0 = ps[0], a1 = ps[1], b0 = pt[0], b1 = pt[1];
                xx[0] = a0.x + b0.x; xx[1] = a0.y + b0.y; xx[2] = a0.z + b0.z; xx[3] = a0.w + b0.w;
                xx[4] = a1.x + b1.x; xx[5] = a1.y + b1.y; xx[6] = a1.z + b1.z; xx[7] = a1.w + b1.w;
                float sum = 0.f, sq = 0.f;
#pragma unroll
                for (int i = 0; i < 8; i++) { sum += xx[i]; sq += xx[i] * xx[i]; }
                sum += __shfl_xor_sync(0xFFFFFFFFu, sum, 1);
                sq  += __shfl_xor_sync(0xFFFFFFFFu, sq, 1);
                sum += __shfl_xor_sync(0xFFFFFFFFu, sum, 2);
                sq  += __shfl_xor_sync(0xFFFFFFFFu, sq, 2);
                float mu = sum * (1.f / 32.f);
                float var = sq * (1.f / 32.f) - mu * mu;
                float rstd = rsqrtf(var + 1e-5f);

                float bag[8];
#pragma unroll
                for (int i = 0; i < 8; i++) bag[i] = 0.f;
                float cnt = 0.f;
#pragma unroll
                for (int b = 0; b < 3; b++) {
                    int a = __ldg(eattr + (size_t)e * 3 + b);
                    if (a != 0) {
                        cnt += 1.f;
                        const float4* pe = reinterpret_cast<const float4*>(
                            emb + (size_t)a * WDIM + c * 64 + sub * 8);
                        float4 e0 = __ldg(pe), e1 = __ldg(pe + 1);
                        bag[0] += e0.x; bag[1] += e0.y; bag[2] += e0.z; bag[3] += e0.w;
                        bag[4] += e1.x; bag[5] += e1.y; bag[6] += e1.z; bag[7] += e1.w;
                    }
                }
                float inv = 1.f / fmaxf(cnt, 1.f);
                float xn[8], gn[8];
#pragma unroll
                for (int i = 0; i < 8; i++) {
                    xn[i] = (xx[i] - mu) * rstd;
                    gn[i] = xn[i] + bag[i] * inv;
                }
                unsigned xh[4], xl[4], gh[4], gl[4];
#pragma unroll
                for (int p = 0; p < 4; p++) {
                    unsigned hp = bf2(xn[2 * p + 1], xn[2 * p]);
                    float h0 = __uint_as_float(hp << 16);
                    float h1 = __uint_as_float(hp & 0xFFFF0000u);
                    xh[p] = hp;
                    xl[p] = bf2(xn[2 * p + 1] - h1, xn[2 * p] - h0);
                    hp = bf2(gn[2 * p + 1], gn[2 * p]);
                    h0 = __uint_as_float(hp << 16);
                    h1 = __uint_as_float(hp & 0xFFFF0000u);
                    gh[p] = hp;
                    gl[p] = bf2(gn[2 * p + 1] - h1, gn[2 * p] - h0);
                }
                asm volatile("st.shared.v4.b32 [%0], {%1,%2,%3,%4};" ::
                             "r"(sb + XNH_O + soff), "r"(xh[0]), "r"(xh[1]), "r"(xh[2]), "r"(xh[3]));
                asm volatile("st.shared.v4.b32 [%0], {%1,%2,%3,%4};" ::
                             "r"(sb + XNL_O + soff), "r"(xl[0]), "r"(xl[1]), "r"(xl[2]), "r"(xl[3]));
                asm volatile("st.shared.v4.b32 [%0], {%1,%2,%3,%4};" ::
                             "r"(sb + GINH_O + soff), "r"(gh[0]), "r"(gh[1]), "r"(gh[2]), "r"(gh[3]));
                asm volatile("st.shared.v4.b32 [%0], {%1,%2,%3,%4};" ::
                             "r"(sb + GINL_O + soff), "r"(gl[0]), "r"(gl[1]), "r"(gl[2]), "r"(gl[3]));
            } else {
                asm volatile("st.shared.v4.b32 [%0], {%1,%1,%1,%1};" :: "r"(sb + XNH_O + soff), "r"(0u));
                asm volatile("st.shared.v4.b32 [%0], {%1,%1,%1,%1};" :: "r"(sb + XNL_O + soff), "r"(0u));
                asm volatile("st.shared.v4.b32 [%0], {%1,%1,%1,%1};" :: "r"(sb + GINH_O + soff), "r"(0u));
                asm volatile("st.shared.v4.b32 [%0], {%1,%1,%1,%1};" :: "r"(sb + GINL_O + soff), "r"(0u));
            }
        }
        asm volatile("cp.async.wait_group 0;" ::: "memory");
        __syncthreads();   // S1: xn/gin + WP(c) visible

        // ---- P2: gate/val HMMA, B-fragments via COALESCED LDG ----
        {
            unsigned bfr[32];
            const uint4* pw = reinterpret_cast<const uint4*>(
                g_wgv_frag + (size_t)(c * 4 + role) * 1024);
#pragma unroll
            for (int i = 0; i < 8; i++) {
                uint4 q = __ldg(pw + i * 32 + lane);   // lanes consecutive 16B
                bfr[i * 4] = q.x; bfr[i * 4 + 1] = q.y;
                bfr[i * 4 + 2] = q.z; bfr[i * 4 + 3] = q.w;
            }
            unsigned agh[2][4], agl[2][4], axh[2][4], axl[2][4];
            unsigned arow = (unsigned)((eg * 16 + (lane & 15)) * 128 + hl * 64 + (lane >> 4) * 16);
#pragma unroll
            for (int ks = 0; ks < 2; ks++) {
                unsigned off = sw128(arow + ks * 32);
                ldm_x4(agh[ks], sb + GINH_O + off);
                ldm_x4(agl[ks], sb + GINL_O + off);
                ldm_x4(axh[ks], sb + XNH_O + off);
                ldm_x4(axl[ks], sb + XNL_O + off);
            }
            float gacc[2][4], vacc[2][4];
#pragma unroll
            for (int j = 0; j < 2; j++)
#pragma unroll
                for (int q = 0; q < 4; q++) { gacc[j][q] = 0.f; vacc[j][q] = 0.f; }
#pragma unroll
            for (int ks = 0; ks < 2; ks++)
#pragma unroll
                for (int j = 0; j < 2; j++) {
                    mma16816(gacc[j], agh[ks], bfr[ks * 4 + 2 * j],      bfr[ks * 4 + 2 * j + 1]);
                    mma16816(gacc[j], agh[ks], bfr[8 + ks * 4 + 2 * j],  bfr[8 + ks * 4 + 2 * j + 1]);
                    mma16816(gacc[j], agl[ks], bfr[ks * 4 + 2 * j],      bfr[ks * 4 + 2 * j + 1]);
                    mma16816(vacc[j], axh[ks], bfr[16 + ks * 4 + 2 * j], bfr[16 + ks * 4 + 2 * j + 1]);
                    mma16816(vacc[j], axh[ks], bfr[24 + ks * 4 + 2 * j], bfr[24 + ks * 4 + 2 * j + 1]);
                    mma16816(vacc[j], axl[ks], bfr[16 + ks * 4 + 2 * j], bfr[16 + ks * 4 + 2 * j + 1]);
                }
#pragma unroll
            for (int j = 0; j < 2; j++)
#pragma unroll
                for (int half = 0; half < 2; half++) {
                    float a0 = fmaxf(gacc[j][half * 2], 0.f) * vacc[j][half * 2];
                    float a1 = fmaxf(gacc[j][half * 2 + 1], 0.f) * vacc[j][half * 2 + 1];
                    int row = eg * 16 + (lane >> 2) + half * 8;
                    int col = hl * 32 + nh * 16 + j * 8 + (lane & 3) * 2;
                    unsigned off = sw128((unsigned)(row * 128 + col * 2));
                    unsigned hp = bf2(a1, a0);
                    float h0 = __uint_as_float(hp << 16);
                    float h1 = __uint_as_float(hp & 0xFFFF0000u);
                    unsigned lp = bf2(a1 - h1, a0 - h0);
                    asm volatile("st.shared.b32 [%0], %1;" :: "r"(sb + ACTH_O + off), "r"(hp));
                    asm volatile("st.shared.b32 [%0], %1;" :: "r"(sb + ACTL_O + off), "r"(lp));
                }
        }
        __syncthreads();   // S2: act visible

        // ---- P3: W_post chunk mainloop (warp tile 32x32, m0 = 0) ----
        {
#pragma unroll
            for (int ks = 0; ks < 4; ks++) {
                unsigned ah[2][4], al[2][4];
#pragma unroll
                for (int mt = 0; mt < 2; mt++) {
                    unsigned off = sw128((unsigned)((mt * 16 + (lane & 15)) * 128
                                                    + ks * 32 + (lane >> 4) * 16));
                    ldm_x4(ah[mt], sb + ACTH_O + off);
                    ldm_x4(al[mt], sb + ACTL_O + off);
                }
#pragma unroll
                for (int nt = 0; nt < 2; nt++) {
                    unsigned off = sw128((unsigned)((n0 + nt * 16 + (lane & 7)
                                                     + ((lane >> 4) & 1) * 8) * 128
                                                    + ks * 32 + ((lane >> 3) & 1) * 16));
                    unsigned bh[4], bl[4];
                    ldm_x4(bh, sb + WPH_O + off);
                    ldm_x4(bl, sb + WPL_O + off);
#pragma unroll
                    for (int j = 0; j < 2; j++) {
                        int nn = nt * 2 + j;
#pragma unroll
                        for (int mt = 0; mt < 2; mt++) {
                            mma16816(acc[mt][nn], ah[mt], bh[2 * j], bh[2 * j + 1]);
                            mma16816(acc[mt][nn], ah[mt], bl[2 * j], bl[2 * j + 1]);
                            mma16816(acc[mt][nn], al[mt], bh[2 * j], bh[2 * j + 1]);
                        }
                    }
                }
            }
        }
        __syncthreads();   // S3: P3 reads done; next chunk may restage WP/act
    }

    // ---- epilogue: scatter ----
#pragma unroll
    for (int mt = 0; mt < 2; mt++) {
        int r0 = mt * 16 + (lane >> 2);
        int r1 = r0 + 8;
        int tg0 = tgt_s[r0], tg1 = tgt_s[r1];
        float* p0 = out + (size_t)(tg0 < 0 ? 0 : tg0) * WDIM;
        float* p1 = out + (size_t)(tg1 < 0 ? 0 : tg1) * WDIM;
#pragma unroll
        for (int nn = 0; nn < 4; nn++) {
            int col = n0 + nn * 8 + (lane & 3) * 2;
            if (tg0 >= 0)
                asm volatile("red.global.add.v2.f32 [%0], {%1,%2};" ::
                             "l"(p0 + col), "f"(acc[mt][nn][0]), "f"(acc[mt][nn][1]) : "memory");
            if (tg1 >= 0)
                asm volatile("red.global.add.v2.f32 [%0], {%1,%2};" ::
                             "l"(p1 + col), "f"(acc[mt][nn][2]), "f"(acc[mt][nn][3]) : "memory");
        }
    }
}

// ---------------------------------------------------------------------------
// K3: out[n,j] *= deg[n]^deg_param[j]
// ---------------------------------------------------------------------------
extern "C" __global__ void scale_kernel(float* __restrict__ out,
                                        const float* __restrict__ deg,
                                        const float* __restrict__ dp, int N)
{
    int idx = blockIdx.x * blockDim.x + threadIdx.x;
    if (idx < N * WDIM) {
        int n = idx >> 8, j = idx & 255;
        out[idx] *= __powf(__ldg(deg + n), __ldg(dp + j));
    }
}

// ---------------------------------------------------------------------------
extern "C" void kernel_launch(void* const* d_in, const int* in_sizes, int n_in,
                              void* d_out, int out_size)
{
    const float* x    = (const float*)d_in[0];
    const float* deg  = (const float*)d_in[1];
    const int*   eidx = (const int*)d_in[2];
    const int*   eattr= (const int*)d_in[3];
    const float* Wsrc = (const float*)d_in[4];
    const float* Wtgt = (const float*)d_in[5];
    const float* emb  = (const float*)d_in[6];
    const float* Wg   = (const float*)d_in[7];
    const float* Wv   = (const float*)d_in[8];
    const float* Wp   = (const float*)d_in[9];
    const float* dp   = (const float*)d_in[10];
    float* out = (float*)d_out;

    int N = in_sizes[0] / WDIM;
    int E = in_sizes[2] / 2;
    int xtotal = in_sizes[0];

    const int NODE_SMEM  = 98304;
    const int FUSED_SMEM = 91136;

    cudaFuncSetAttribute(hmma_node_kernel,
                         cudaFuncAttributeMaxDynamicSharedMemorySize, NODE_SMEM);
    cudaFuncSetAttribute(fused_edge_kernel,
                         cudaFuncAttributeMaxDynamicSharedMemorySize, FUSED_SMEM);

    cudaMemsetAsync(d_out, 0, (size_t)out_size * sizeof(float));

    xsplit_kernel<<<(xtotal + 511) / 512, 512>>>(x, xtotal);
    wsplit_kernel<<<64, 1024>>>(Wp, Wsrc, Wtgt, Wg, Wv);
    dim3 ng((N + 127) / 128, 2);
    hmma_node_kernel<<<ng, 512, NODE_SMEM>>>(N);
    fused_edge_kernel<<<(E + 31) / 32, 256, FUSED_SMEM>>>(eidx, eattr, emb, out, E);
    scale_kernel<<<((size_t)N * WDIM + 511) / 512, 512>>>(out, deg, dp, N);
}

// round 16
// speedup vs baseline: 1.4571x; 1.1010x over previous
#include <cuda_runtime.h>
#include <cuda_bf16.h>
#include <cstdint>

#define WDIM 256

// ---------------------------------------------------------------------------
// Scratch (device globals)
// ---------------------------------------------------------------------------
__device__ float g_xs[2560000];              // [N,256]
__device__ float g_xt[2560000];
__device__ unsigned short g_x_hi[2560000];   // x bf16 hi/lo [N,256]
__device__ unsigned short g_x_lo[2560000];
__device__ unsigned short g_wsrc_hi[65536];  // W_src bf16 hi/lo [n,k]
__device__ unsigned short g_wsrc_lo[65536];
__device__ unsigned short g_wtgt_hi[65536];
__device__ unsigned short g_wtgt_lo[65536];
// gate/val weights as m16n8k16 B-fragments, lane-coalesced (R14-validated):
// u32 index = ((((c*4 + role)*8 + i)*32 + lane)*4 + q), slot = i*4 + q
__device__ unsigned g_wgv_frag[16384];
// W_post as m16n8k16 B-fragments, lane-coalesced:
// u32 index = ((((c*4 + ks)*8 + w)*2 + nt)*32 + lane)*4 + r   (32768 u32!)
//   r: j = r>>1 (8-col group), p = r&1 (k-half);
//   n = w*32 + nt*16 + j*8 + (lane>>2), k = c*64 + ks*16 + p*8 + 2*(lane&3)
__device__ unsigned g_wpf_hi[32768];
__device__ unsigned g_wpf_lo[32768];

typedef unsigned long long u64;

__device__ __forceinline__ unsigned sw128(unsigned x) { return x ^ ((x >> 3) & 0x70u); }
__device__ __forceinline__ void cpa16(unsigned dst, const void* src) {
    asm volatile("cp.async.cg.shared.global [%0], [%1], 16;" :: "r"(dst), "l"(src));
}
__device__ __forceinline__ void zfill16(unsigned dst) {
    asm volatile("st.shared.v4.b32 [%0], {%1,%1,%1,%1};" :: "r"(dst), "r"(0u));
}
__device__ __forceinline__ void ldm_x4(unsigned* r, unsigned addr) {
    asm volatile("ldmatrix.sync.aligned.m8n8.x4.shared.b16 {%0,%1,%2,%3}, [%4];"
                 : "=r"(r[0]), "=r"(r[1]), "=r"(r[2]), "=r"(r[3]) : "r"(addr));
}
__device__ __forceinline__ void mma16816(float* d, const unsigned* a,
                                         unsigned b0, unsigned b1) {
    asm volatile(
        "mma.sync.aligned.m16n8k16.row.col.f32.bf16.bf16.f32 "
        "{%0,%1,%2,%3}, {%4,%5,%6,%7}, {%8,%9}, {%0,%1,%2,%3};"
        : "+f"(d[0]), "+f"(d[1]), "+f"(d[2]), "+f"(d[3])
        : "r"(a[0]), "r"(a[1]), "r"(a[2]), "r"(a[3]), "r"(b0), "r"(b1));
}
// pack 2 fp32 -> bf16x2 (hi16 = a1, lo16 = a0)
__device__ __forceinline__ unsigned bf2(float a1, float a0) {
    unsigned d;
    asm("cvt.rn.bf16x2.f32 %0, %1, %2;" : "=r"(d) : "f"(a1), "f"(a0));
    return d;
}

// ---------------------------------------------------------------------------
// Split x into bf16 hi/lo
// ---------------------------------------------------------------------------
extern "C" __global__ void xsplit_kernel(const float* __restrict__ x, int total)
{
    int i = blockIdx.x * blockDim.x + threadIdx.x;
    if (i < total) {
        float v = x[i];
        __nv_bfloat16 h = __float2bfloat16(v);
        float lof = v - __bfloat162float(h);
        __nv_bfloat16 l = __float2bfloat16(lof);
        g_x_hi[i] = *reinterpret_cast<unsigned short*>(&h);
        g_x_lo[i] = *reinterpret_cast<unsigned short*>(&l);
    }
}

// ---------------------------------------------------------------------------
// Weight preprocessing: Wsrc/Wtgt hi/lo + WGV fragments + WP fragments
// ---------------------------------------------------------------------------
extern "C" __global__ void wsplit_kernel(const float* __restrict__ Wp,
                                         const float* __restrict__ Ws,
                                         const float* __restrict__ Wt,
                                         const float* __restrict__ Wg,
                                         const float* __restrict__ Wv)
{
    int m = blockIdx.x * blockDim.x + threadIdx.x;
    if (m < 65536) {
        {
            float v = Ws[m];
            __nv_bfloat16 h = __float2bfloat16(v);
            float lof = v - __bfloat162float(h);
            __nv_bfloat16 l = __float2bfloat16(lof);
            g_wsrc_hi[m] = *reinterpret_cast<unsigned short*>(&h);
            g_wsrc_lo[m] = *reinterpret_cast<unsigned short*>(&l);
        }
        {
            float v = Wt[m];
            __nv_bfloat16 h = __float2bfloat16(v);
            float lof = v - __bfloat162float(h);
            __nv_bfloat16 l = __float2bfloat16(lof);
            g_wtgt_hi[m] = *reinterpret_cast<unsigned short*>(&h);
            g_wtgt_lo[m] = *reinterpret_cast<unsigned short*>(&l);
        }
    }
    if (m < 16384) {
        // WGV fragments (R14-validated lane-coalesced layout)
        int q    = m & 3;
        int lane = (m >> 2) & 31;
        int i    = (m >> 7) & 7;
        int role = (m >> 10) & 3;
        int c    = m >> 12;
        int slot = i * 4 + q;
        int hl   = role >> 1, nh = role & 1;
        int mt   = slot >> 3;
        int r8 = slot & 7;
        int ks = r8 >> 2;
        int r  = r8 & 3;
        int j  = r >> 1, p = r & 1;
        int h = c * 2 + hl;
        int f = nh * 16 + j * 8 + (lane >> 2);
        int d = ks * 16 + p * 8 + 2 * (lane & 3);
        const float* Wm = (mt < 2) ? Wg : Wv;
        float v0 = Wm[(size_t)h * 1024 + f * 32 + d];
        float v1 = Wm[(size_t)h * 1024 + f * 32 + d + 1];
        if ((mt & 1) == 0) {
            g_wgv_frag[m] = bf2(v1, v0);
        } else {
            float h0 = __bfloat162float(__float2bfloat16(v0));
            float h1 = __bfloat162float(__float2bfloat16(v1));
            g_wgv_frag[m] = bf2(v1 - h1, v0 - h0);
        }
    }
    if (m < 32768) {
        // WP fragments: decode mirrors P3 consumption exactly (32768 u32)
        int r    = m & 3;
        int lane = (m >> 2) & 31;
        int nt   = (m >> 7) & 1;
        int w    = (m >> 8) & 7;
        int ks   = (m >> 11) & 3;
        int c    = m >> 13;
        int j = r >> 1, p = r & 1;
        int n = w * 32 + nt * 16 + j * 8 + (lane >> 2);
        int k = c * 64 + ks * 16 + p * 8 + 2 * (lane & 3);
        float v0 = Wp[(size_t)n * 256 + k];
        float v1 = Wp[(size_t)n * 256 + k + 1];
        float h0 = __bfloat162float(__float2bfloat16(v0));
        float h1 = __bfloat162float(__float2bfloat16(v1));
        g_wpf_hi[m] = bf2(v1, v0);
        g_wpf_lo[m] = bf2(v1 - h1, v0 - h0);
    }
}

// ---------------------------------------------------------------------------
// K1: HMMA node GEMM (R10, unchanged). Block = 128 nodes x 256 outs.
// ---------------------------------------------------------------------------
extern "C" __global__ void __launch_bounds__(512, 1)
hmma_node_kernel(int N)
{
    extern __shared__ char smc[];
    unsigned sb = (unsigned)__cvta_generic_to_shared(smc);
    const unsigned A_HI = sb, A_LO = sb + 16384u, B_HI = sb + 32768u, B_LO = sb + 65536u;
    const int t = threadIdx.x, lane = t & 31, wid = t >> 5;
    const int wm = wid & 3, wn = wid >> 2;
    const int m0 = wm * 32, n0 = wn * 64;
    const int nb = blockIdx.x * 128;
    const unsigned short* Wh = blockIdx.y ? g_wtgt_hi : g_wsrc_hi;
    const unsigned short* Wl = blockIdx.y ? g_wtgt_lo : g_wsrc_lo;
    float* og = blockIdx.y ? g_xt : g_xs;

    float acc[2][8][4];
#pragma unroll
    for (int mt = 0; mt < 2; mt++)
#pragma unroll
        for (int nn = 0; nn < 8; nn++)
#pragma unroll
            for (int q = 0; q < 4; q++) acc[mt][nn][q] = 0.f;

#pragma unroll 1
    for (int c = 0; c < 4; c++) {
        __syncthreads();
#pragma unroll
        for (int i = 0; i < 2; i++) {
            int u = t + 512 * i;
            int r = u >> 3, q = u & 7;
            unsigned off = sw128((unsigned)(r * 128 + q * 16));
            int row = nb + r;
            if (row < N) {
                cpa16(A_HI + off, g_x_hi + (size_t)row * 256 + c * 64 + q * 8);
                cpa16(A_LO + off, g_x_lo + (size_t)row * 256 + c * 64 + q * 8);
            } else {
                zfill16(A_HI + off);
                zfill16(A_LO + off);
            }
        }
#pragma unroll
        for (int i = 0; i < 4; i++) {
            int u = t + 512 * i;
            int n = u >> 3, q = u & 7;
            unsigned off = sw128((unsigned)(n * 128 + q * 16));
            cpa16(B_HI + off, Wh + (size_t)n * 256 + c * 64 + q * 8);
            cpa16(B_LO + off, Wl + (size_t)n * 256 + c * 64 + q * 8);
        }
        asm volatile("cp.async.commit_group;" ::: "memory");
        asm volatile("cp.async.wait_group 0;" ::: "memory");
        __syncthreads();

#pragma unroll
        for (int ks = 0; ks < 4; ks++) {
            unsigned ah[2][4], al[2][4];
#pragma unroll
            for (int mt = 0; mt < 2; mt++) {
                unsigned off = sw128((unsigned)((m0 + mt * 16 + (lane & 15)) * 128
                                                + ks * 32 + (lane >> 4) * 16));
                ldm_x4(ah[mt], A_HI + off);
                ldm_x4(al[mt], A_LO + off);
            }
#pragma unroll
            for (int nt = 0; nt < 4; nt++) {
                unsigned off = sw128((unsigned)((n0 + nt * 16 + (lane & 7)
                                                 + ((lane >> 4) & 1) * 8) * 128
                                                + ks * 32 + ((lane >> 3) & 1) * 16));
                unsigned bh[4], bl[4];
                ldm_x4(bh, B_HI + off);
                ldm_x4(bl, B_LO + off);
#pragma unroll
                for (int j = 0; j < 2; j++) {
                    int nn = nt * 2 + j;
#pragma unroll
                    for (int mt = 0; mt < 2; mt++) {
                        mma16816(acc[mt][nn], ah[mt], bh[2 * j], bh[2 * j + 1]);
                        mma16816(acc[mt][nn], ah[mt], bl[2 * j], bl[2 * j + 1]);
                        mma16816(acc[mt][nn], al[mt], bh[2 * j], bh[2 * j + 1]);
                    }
                }
            }
        }
    }

#pragma unroll
    for (int mt = 0; mt < 2; mt++) {
        int r0 = nb + m0 + mt * 16 + (lane >> 2);
        int r1 = r0 + 8;
#pragma unroll
        for (int nn = 0; nn < 8; nn++) {
            int col = n0 + nn * 8 + (lane & 3) * 2;
            if (r0 < N) {
                og[(size_t)r0 * WDIM + col]     = acc[mt][nn][0];
                og[(size_t)r0 * WDIM + col + 1] = acc[mt][nn][1];
            }
            if (r1 < N) {
                og[(size_t)r1 * WDIM + col]     = acc[mt][nn][2];
                og[(size_t)r1 * WDIM + col + 1] = acc[mt][nn][3];
            }
        }
    }
}

// ---------------------------------------------------------------------------
// K2 (fused), R16 = R15 with correctly sized WP fragment tables.
// All weights via coalesced LDG fragments; no cp.async; 2 barriers/chunk.
// Each CTA: 32 edges x 256 cols, 256 thr, 2 CTAs/SM. smem 25600 B.
// ---------------------------------------------------------------------------
#define XNH_O  1024u
#define XNL_O  5120u
#define GINH_O 9216u
#define GINL_O 13312u
#define ACTH_O 17408u
#define ACTL_O 21504u

extern "C" __global__ void __launch_bounds__(256, 2)
fused_edge_kernel(const int* __restrict__ eidx, const int* __restrict__ eattr,
                  const float* __restrict__ emb, float* __restrict__ out, int E)
{
    extern __shared__ char smc[];
    unsigned sb = (unsigned)__cvta_generic_to_shared(smc);
    int* tgt_s = reinterpret_cast<int*>(smc);
    const int t = threadIdx.x, lane = t & 31, wid = t >> 5;
    const int eb = blockIdx.x * 32;

    if (t < 32) {
        int e = eb + t;
        tgt_s[t] = (e < E) ? __ldg(eidx + E + e) : -1;
    }
    __syncthreads();

    const int n0 = wid * 32;
    float acc[2][4][4];
#pragma unroll
    for (int mt = 0; mt < 2; mt++)
#pragma unroll
        for (int nn = 0; nn < 4; nn++)
#pragma unroll
            for (int q = 0; q < 4; q++) acc[mt][nn][q] = 0.f;

    const int e_l = t >> 3, sub = t & 7;
    const int e = eb + e_l;
    const int eg = wid >> 2, hl = (wid >> 1) & 1, nh = wid & 1;
    const int role = wid & 3;

#pragma unroll 1
    for (int c = 0; c < 4; c++) {
        // ---- P1: xn/gin for this chunk's 2 heads ----
        {
            unsigned soff = sw128((unsigned)(e_l * 128 + sub * 16));
            if (e < E) {
                int s  = __ldg(eidx + e);
                int tg = tgt_s[e_l];
                const float4* ps = reinterpret_cast<const float4*>(
                    g_xs + (size_t)s * WDIM + c * 64 + sub * 8);
                const float4* pt = reinterpret_cast<const float4*>(
                    g_xt + (size_t)tg * WDIM + c * 64 + sub * 8);
                float xx[8];
                float4 a0 = ps[0], a1 = ps[1], b0 = pt[0], b1 = pt[1];
                xx[0] = a0.x + b0.x; xx[1] = a0.y + b0.y; xx[2] = a0.z + b0.z; xx[3] = a0.w + b0.w;
                xx[4] = a1.x + b1.x; xx[5] = a1.y + b1.y; xx[6] = a1.z + b1.z; xx[7] = a1.w + b1.w;
                float sum = 0.f, sq = 0.f;
#pragma unroll
                for (int i = 0; i < 8; i++) { sum += xx[i]; sq += xx[i] * xx[i]; }
                sum += __shfl_xor_sync(0xFFFFFFFFu, sum, 1);
                sq  += __shfl_xor_sync(0xFFFFFFFFu, sq, 1);
                sum += __shfl_xor_sync(0xFFFFFFFFu, sum, 2);
                sq  += __shfl_xor_sync(0xFFFFFFFFu, sq, 2);
                float mu = sum * (1.f / 32.f);
                float var = sq * (1.f / 32.f) - mu * mu;
                float rstd = rsqrtf(var + 1e-5f);

                float bag[8];
#pragma unroll
                for (int i = 0; i < 8; i++) bag[i] = 0.f;
                float cnt = 0.f;
#pragma unroll
                for (int b = 0; b < 3; b++) {
                    int a = __ldg(eattr + (size_t)e * 3 + b);
                    if (a != 0) {
                        cnt += 1.f;
                        const float4* pe = reinterpret_cast<const float4*>(
                            emb + (size_t)a * WDIM + c * 64 + sub * 8);
                        float4 e0 = __ldg(pe), e1 = __ldg(pe + 1);
                        bag[0] += e0.x; bag[1] += e0.y; bag[2] += e0.z; bag[3] += e0.w;
                        bag[4] += e1.x; bag[5] += e1.y; bag[6] += e1.z; bag[7] += e1.w;
                    }
                }
                float inv = 1.f / fmaxf(cnt, 1.f);
                float xn[8], gn[8];
#pragma unroll
                for (int i = 0; i < 8; i++) {
                    xn[i] = (xx[i] - mu) * rstd;
                    gn[i] = xn[i] + bag[i] * inv;
                }
                unsigned xh[4], xl[4], gh[4], gl[4];
#pragma unroll
                for (int p = 0; p < 4; p++) {
                    unsigned hp = bf2(xn[2 * p + 1], xn[2 * p]);
                    float h0 = __uint_as_float(hp << 16);
                    float h1 = __uint_as_float(hp & 0xFFFF0000u);
                    xh[p] = hp;
                    xl[p] = bf2(xn[2 * p + 1] - h1, xn[2 * p] - h0);
                    hp = bf2(gn[2 * p + 1], gn[2 * p]);
                    h0 = __uint_as_float(hp << 16);
                    h1 = __uint_as_float(hp & 0xFFFF0000u);
                    gh[p] = hp;
                    gl[p] = bf2(gn[2 * p + 1] - h1, gn[2 * p] - h0);
                }
                asm volatile("st.shared.v4.b32 [%0], {%1,%2,%3,%4};" ::
                             "r"(sb + XNH_O + soff), "r"(xh[0]), "r"(xh[1]), "r"(xh[2]), "r"(xh[3]));
                asm volatile("st.shared.v4.b32 [%0], {%1,%2,%3,%4};" ::
                             "r"(sb + XNL_O + soff), "r"(xl[0]), "r"(xl[1]), "r"(xl[2]), "r"(xl[3]));
                asm volatile("st.shared.v4.b32 [%0], {%1,%2,%3,%4};" ::
                             "r"(sb + GINH_O + soff), "r"(gh[0]), "r"(gh[1]), "r"(gh[2]), "r"(gh[3]));
                asm volatile("st.shared.v4.b32 [%0], {%1,%2,%3,%4};" ::
                             "r"(sb + GINL_O + soff), "r"(gl[0]), "r"(gl[1]), "r"(gl[2]), "r"(gl[3]));
            } else {
                asm volatile("st.shared.v4.b32 [%0], {%1,%1,%1,%1};" :: "r"(sb + XNH_O + soff), "r"(0u));
                asm volatile("st.shared.v4.b32 [%0], {%1,%1,%1,%1};" :: "r"(sb + XNL_O + soff), "r"(0u));
                asm volatile("st.shared.v4.b32 [%0], {%1,%1,%1,%1};" :: "r"(sb + GINH_O + soff), "r"(0u));
                asm volatile("st.shared.v4.b32 [%0], {%1,%1,%1,%1};" :: "r"(sb + GINL_O + soff), "r"(0u));
            }
        }
        __syncthreads();   // S1: xn/gin visible

        // ---- P2: gate/val HMMA, WGV fragments via coalesced LDG ----
        {
            unsigned bfr[32];
            const uint4* pw = reinterpret_cast<const uint4*>(
                g_wgv_frag + (size_t)(c * 4 + role) * 1024);
#pragma unroll
            for (int i = 0; i < 8; i++) {
                uint4 q = __ldg(pw + i * 32 + lane);
                bfr[i * 4] = q.x; bfr[i * 4 + 1] = q.y;
                bfr[i * 4 + 2] = q.z; bfr[i * 4 + 3] = q.w;
            }
            unsigned agh[2][4], agl[2][4], axh[2][4], axl[2][4];
            unsigned arow = (unsigned)((eg * 16 + (lane & 15)) * 128 + hl * 64 + (lane >> 4) * 16);
#pragma unroll
            for (int ks = 0; ks < 2; ks++) {
                unsigned off = sw128(arow + ks * 32);
                ldm_x4(agh[ks], sb + GINH_O + off);
                ldm_x4(agl[ks], sb + GINL_O + off);
                ldm_x4(axh[ks], sb + XNH_O + off);
                ldm_x4(axl[ks], sb + XNL_O + off);
            }
            float gacc[2][4], vacc[2][4];
#pragma unroll
            for (int j = 0; j < 2; j++)
#pragma unroll
                for (int q = 0; q < 4; q++) { gacc[j][q] = 0.f; vacc[j][q] = 0.f; }
#pragma unroll
            for (int ks = 0; ks < 2; ks++)
#pragma unroll
                for (int j = 0; j < 2; j++) {
                    mma16816(gacc[j], agh[ks], bfr[ks * 4 + 2 * j],      bfr[ks * 4 + 2 * j + 1]);
                    mma16816(gacc[j], agh[ks], bfr[8 + ks * 4 + 2 * j],  bfr[8 + ks * 4 + 2 * j + 1]);
                    mma16816(gacc[j], agl[ks], bfr[ks * 4 + 2 * j],      bfr[ks * 4 + 2 * j + 1]);
                    mma16816(vacc[j], axh[ks], bfr[16 + ks * 4 + 2 * j], bfr[16 + ks * 4 + 2 * j + 1]);
                    mma16816(vacc[j], axh[ks], bfr[24 + ks * 4 + 2 * j], bfr[24 + ks * 4 + 2 * j + 1]);
                    mma16816(vacc[j], axl[ks], bfr[16 + ks * 4 + 2 * j], bfr[16 + ks * 4 + 2 * j + 1]);
                }
#pragma unroll
            for (int j = 0; j < 2; j++)
#pragma unroll
                for (int half = 0; half < 2; half++) {
                    float a0 = fmaxf(gacc[j][half * 2], 0.f) * vacc[j][half * 2];
                    float a1 = fmaxf(gacc[j][half * 2 + 1], 0.f) * vacc[j][half * 2 + 1];
                    int row = eg * 16 + (lane >> 2) + half * 8;
                    int col = hl * 32 + nh * 16 + j * 8 + (lane & 3) * 2;
                    unsigned off = sw128((unsigned)(row * 128 + col * 2));
                    unsigned hp = bf2(a1, a0);
                    float h0 = __uint_as_float(hp << 16);
                    float h1 = __uint_as_float(hp & 0xFFFF0000u);
                    unsigned lp = bf2(a1 - h1, a0 - h0);
                    asm volatile("st.shared.b32 [%0], %1;" :: "r"(sb + ACTH_O + off), "r"(hp));
                    asm volatile("st.shared.b32 [%0], %1;" :: "r"(sb + ACTL_O + off), "r"(lp));
                }
        }
        __syncthreads();   // S2: act visible

        // ---- P3: W_post mainloop, WP fragments via coalesced LDG ----
        {
            const uint4* pwh = reinterpret_cast<const uint4*>(g_wpf_hi);
            const uint4* pwl = reinterpret_cast<const uint4*>(g_wpf_lo);
#pragma unroll
            for (int ks = 0; ks < 4; ks++) {
                unsigned ah[2][4], al[2][4];
#pragma unroll
                for (int mt = 0; mt < 2; mt++) {
                    unsigned off = sw128((unsigned)((mt * 16 + (lane & 15)) * 128
                                                    + ks * 32 + (lane >> 4) * 16));
                    ldm_x4(ah[mt], sb + ACTH_O + off);
                    ldm_x4(al[mt], sb + ACTL_O + off);
                }
#pragma unroll
                for (int nt = 0; nt < 2; nt++) {
                    unsigned idx = (unsigned)((((c * 4 + ks) * 8 + wid) * 2 + nt) * 32 + lane);
                    uint4 qh = __ldg(pwh + idx);
                    uint4 ql = __ldg(pwl + idx);
                    unsigned bh[4] = {qh.x, qh.y, qh.z, qh.w};
                    unsigned bl[4] = {ql.x, ql.y, ql.z, ql.w};
#pragma unroll
                    for (int j = 0; j < 2; j++) {
                        int nn = nt * 2 + j;
#pragma unroll
                        for (int mt = 0; mt < 2; mt++) {
                            mma16816(acc[mt][nn], ah[mt], bh[2 * j], bh[2 * j + 1]);
                            mma16816(acc[mt][nn], ah[mt], bl[2 * j], bl[2 * j + 1]);
                            mma16816(acc[mt][nn], al[mt], bh[2 * j], bh[2 * j + 1]);
                        }
                    }
                }
            }
        }
        // no chunk-end barrier (act(c+1) written only after S1(c+1))
    }

    // ---- epilogue: scatter ----
#pragma unroll
    for (int mt = 0; mt < 2; mt++) {
        int r0 = mt * 16 + (lane >> 2);
        int r1 = r0 + 8;
        int tg0 = tgt_s[r0], tg1 = tgt_s[r1];
        float* p0 = out + (size_t)(tg0 < 0 ? 0 : tg0) * WDIM;
        float* p1 = out + (size_t)(tg1 < 0 ? 0 : tg1) * WDIM;
#pragma unroll
        for (int nn = 0; nn < 4; nn++) {
            int col = n0 + nn * 8 + (lane & 3) * 2;
            if (tg0 >= 0)
                asm volatile("red.global.add.v2.f32 [%0], {%1,%2};" ::
                             "l"(p0 + col), "f"(acc[mt][nn][0]), "f"(acc[mt][nn][1]) : "memory");
            if (tg1 >= 0)
                asm volatile("red.global.add.v2.f32 [%0], {%1,%2};" ::
                             "l"(p1 + col), "f"(acc[mt][nn][2]), "f"(acc[mt][nn][3]) : "memory");
        }
    }
}

// ---------------------------------------------------------------------------
// K3: out[n,j] *= deg[n]^deg_param[j]
// ---------------------------------------------------------------------------
extern "C" __global__ void scale_kernel(float* __restrict__ out,
                                        const float* __restrict__ deg,
                                        const float* __restrict__ dp, int N)
{
    int idx = blockIdx.x * blockDim.x + threadIdx.x;
    if (idx < N * WDIM) {
        int n = idx >> 8, j = idx & 255;
        out[idx] *= __powf(__ldg(deg + n), __ldg(dp + j));
    }
}

// ---------------------------------------------------------------------------
extern "C" void kernel_launch(void* const* d_in, const int* in_sizes, int n_in,
                              void* d_out, int out_size)
{
    const float* x    = (const float*)d_in[0];
    const float* deg  = (const float*)d_in[1];
    const int*   eidx = (const int*)d_in[2];
    const int*   eattr= (const int*)d_in[3];
    const float* Wsrc = (const float*)d_in[4];
    const float* Wtgt = (const float*)d_in[5];
    const float* emb  = (const float*)d_in[6];
    const float* Wg   = (const float*)d_in[7];
    const float* Wv   = (const float*)d_in[8];
    const float* Wp   = (const float*)d_in[9];
    const float* dp   = (const float*)d_in[10];
    float* out = (float*)d_out;

    int N = in_sizes[0] / WDIM;
    int E = in_sizes[2] / 2;
    int xtotal = in_sizes[0];

    const int NODE_SMEM  = 98304;
    const int FUSED_SMEM = 25600;

    cudaFuncSetAttribute(hmma_node_kernel,
                         cudaFuncAttributeMaxDynamicSharedMemorySize, NODE_SMEM);
    cudaFuncSetAttribute(fused_edge_kernel,
                         cudaFuncAttributeMaxDynamicSharedMemorySize, FUSED_SMEM);

    cudaMemsetAsync(d_out, 0, (size_t)out_size * sizeof(float));

    xsplit_kernel<<<(xtotal + 511) / 512, 512>>>(x, xtotal);
    wsplit_kernel<<<64, 1024>>>(Wp, Wsrc, Wtgt, Wg, Wv);
    dim3 ng((N + 127) / 128, 2);
    hmma_node_kernel<<<ng, 512, NODE_SMEM>>>(N);
    fused_edge_kernel<<<(E + 31) / 32, 256, FUSED_SMEM>>>(eidx, eattr, emb, out, E);
    scale_kernel<<<((size_t)N * WDIM + 511) / 512, 512>>>(out, deg, dp, N);
}

// round 17
// speedup vs baseline: 1.5476x; 1.0621x over previous
#include <cuda_runtime.h>
#include <cuda_bf16.h>
#include <cstdint>

#define WDIM 256

// ---------------------------------------------------------------------------
// Scratch (device globals)
// ---------------------------------------------------------------------------
__device__ float g_xs[2560000];              // [N,256]
__device__ float g_xt[2560000];
__device__ unsigned short g_x_hi[2560000];   // x bf16 hi/lo [N,256]
__device__ unsigned short g_x_lo[2560000];
__device__ unsigned short g_wsrc_hi[65536];  // W_src bf16 hi/lo [n,k]
__device__ unsigned short g_wsrc_lo[65536];
__device__ unsigned short g_wtgt_hi[65536];
__device__ unsigned short g_wtgt_lo[65536];
// gate/val weights as m16n8k16 B-fragments, lane-coalesced (R14-validated):
// u32 index = ((((c*4 + role)*8 + i)*32 + lane)*4 + q), slot = i*4 + q
__device__ unsigned g_wgv_frag[16384];
// W_post as m16n8k16 B-fragments, lane-coalesced (R16-validated, 32768 u32):
// u32 index = ((((c*4 + ks)*8 + w)*2 + nt)*32 + lane)*4 + r
__device__ unsigned g_wpf_hi[32768];
__device__ unsigned g_wpf_lo[32768];

typedef unsigned long long u64;

__device__ __forceinline__ unsigned sw128(unsigned x) { return x ^ ((x >> 3) & 0x70u); }
__device__ __forceinline__ void cpa16(unsigned dst, const void* src) {
    asm volatile("cp.async.cg.shared.global [%0], [%1], 16;" :: "r"(dst), "l"(src));
}
__device__ __forceinline__ void zfill16(unsigned dst) {
    asm volatile("st.shared.v4.b32 [%0], {%1,%1,%1,%1};" :: "r"(dst), "r"(0u));
}
__device__ __forceinline__ void ldm_x4(unsigned* r, unsigned addr) {
    asm volatile("ldmatrix.sync.aligned.m8n8.x4.shared.b16 {%0,%1,%2,%3}, [%4];"
                 : "=r"(r[0]), "=r"(r[1]), "=r"(r[2]), "=r"(r[3]) : "r"(addr));
}
__device__ __forceinline__ void mma16816(float* d, const unsigned* a,
                                         unsigned b0, unsigned b1) {
    asm volatile(
        "mma.sync.aligned.m16n8k16.row.col.f32.bf16.bf16.f32 "
        "{%0,%1,%2,%3}, {%4,%5,%6,%7}, {%8,%9}, {%0,%1,%2,%3};"
        : "+f"(d[0]), "+f"(d[1]), "+f"(d[2]), "+f"(d[3])
        : "r"(a[0]), "r"(a[1]), "r"(a[2]), "r"(a[3]), "r"(b0), "r"(b1));
}
// pack 2 fp32 -> bf16x2 (hi16 = a1, lo16 = a0)
__device__ __forceinline__ unsigned bf2(float a1, float a0) {
    unsigned d;
    asm("cvt.rn.bf16x2.f32 %0, %1, %2;" : "=r"(d) : "f"(a1), "f"(a0));
    return d;
}

// ---------------------------------------------------------------------------
// Split x into bf16 hi/lo
// ---------------------------------------------------------------------------
extern "C" __global__ void xsplit_kernel(const float* __restrict__ x, int total)
{
    int i = blockIdx.x * blockDim.x + threadIdx.x;
    if (i < total) {
        float v = x[i];
        __nv_bfloat16 h = __float2bfloat16(v);
        float lof = v - __bfloat162float(h);
        __nv_bfloat16 l = __float2bfloat16(lof);
        g_x_hi[i] = *reinterpret_cast<unsigned short*>(&h);
        g_x_lo[i] = *reinterpret_cast<unsigned short*>(&l);
    }
}

// ---------------------------------------------------------------------------
// Weight preprocessing: Wsrc/Wtgt hi/lo + WGV fragments + WP fragments
// ---------------------------------------------------------------------------
extern "C" __global__ void wsplit_kernel(const float* __restrict__ Wp,
                                         const float* __restrict__ Ws,
                                         const float* __restrict__ Wt,
                                         const float* __restrict__ Wg,
                                         const float* __restrict__ Wv)
{
    int m = blockIdx.x * blockDim.x + threadIdx.x;
    if (m < 65536) {
        {
            float v = Ws[m];
            __nv_bfloat16 h = __float2bfloat16(v);
            float lof = v - __bfloat162float(h);
            __nv_bfloat16 l = __float2bfloat16(lof);
            g_wsrc_hi[m] = *reinterpret_cast<unsigned short*>(&h);
            g_wsrc_lo[m] = *reinterpret_cast<unsigned short*>(&l);
        }
        {
            float v = Wt[m];
            __nv_bfloat16 h = __float2bfloat16(v);
            float lof = v - __bfloat162float(h);
            __nv_bfloat16 l = __float2bfloat16(lof);
            g_wtgt_hi[m] = *reinterpret_cast<unsigned short*>(&h);
            g_wtgt_lo[m] = *reinterpret_cast<unsigned short*>(&l);
        }
    }
    if (m < 16384) {
        // WGV fragments (R14-validated lane-coalesced layout)
        int q    = m & 3;
        int lane = (m >> 2) & 31;
        int i    = (m >> 7) & 7;
        int role = (m >> 10) & 3;
        int c    = m >> 12;
        int slot = i * 4 + q;
        int hl   = role >> 1, nh = role & 1;
        int mt   = slot >> 3;
        int r8 = slot & 7;
        int ks = r8 >> 2;
        int r  = r8 & 3;
        int j  = r >> 1, p = r & 1;
        int h = c * 2 + hl;
        int f = nh * 16 + j * 8 + (lane >> 2);
        int d = ks * 16 + p * 8 + 2 * (lane & 3);
        const float* Wm = (mt < 2) ? Wg : Wv;
        float v0 = Wm[(size_t)h * 1024 + f * 32 + d];
        float v1 = Wm[(size_t)h * 1024 + f * 32 + d + 1];
        if ((mt & 1) == 0) {
            g_wgv_frag[m] = bf2(v1, v0);
        } else {
            float h0 = __bfloat162float(__float2bfloat16(v0));
            float h1 = __bfloat162float(__float2bfloat16(v1));
            g_wgv_frag[m] = bf2(v1 - h1, v0 - h0);
        }
    }
    if (m < 32768) {
        // WP fragments (R16-validated)
        int r    = m & 3;
        int lane = (m >> 2) & 31;
        int nt   = (m >> 7) & 1;
        int w    = (m >> 8) & 7;
        int ks   = (m >> 11) & 3;
        int c    = m >> 13;
        int j = r >> 1, p = r & 1;
        int n = w * 32 + nt * 16 + j * 8 + (lane >> 2);
        int k = c * 64 + ks * 16 + p * 8 + 2 * (lane & 3);
        float v0 = Wp[(size_t)n * 256 + k];
        float v1 = Wp[(size_t)n * 256 + k + 1];
        float h0 = __bfloat162float(__float2bfloat16(v0));
        float h1 = __bfloat162float(__float2bfloat16(v1));
        g_wpf_hi[m] = bf2(v1, v0);
        g_wpf_lo[m] = bf2(v1 - h1, v0 - h0);
    }
}

// ---------------------------------------------------------------------------
// K1: HMMA node GEMM (R10, unchanged). Block = 128 nodes x 256 outs.
// ---------------------------------------------------------------------------
extern "C" __global__ void __launch_bounds__(512, 1)
hmma_node_kernel(int N)
{
    extern __shared__ char smc[];
    unsigned sb = (unsigned)__cvta_generic_to_shared(smc);
    const unsigned A_HI = sb, A_LO = sb + 16384u, B_HI = sb + 32768u, B_LO = sb + 65536u;
    const int t = threadIdx.x, lane = t & 31, wid = t >> 5;
    const int wm = wid & 3, wn = wid >> 2;
    const int m0 = wm * 32, n0 = wn * 64;
    const int nb = blockIdx.x * 128;
    const unsigned short* Wh = blockIdx.y ? g_wtgt_hi : g_wsrc_hi;
    const unsigned short* Wl = blockIdx.y ? g_wtgt_lo : g_wsrc_lo;
    float* og = blockIdx.y ? g_xt : g_xs;

    float acc[2][8][4];
#pragma unroll
    for (int mt = 0; mt < 2; mt++)
#pragma unroll
        for (int nn = 0; nn < 8; nn++)
#pragma unroll
            for (int q = 0; q < 4; q++) acc[mt][nn][q] = 0.f;

#pragma unroll 1
    for (int c = 0; c < 4; c++) {
        __syncthreads();
#pragma unroll
        for (int i = 0; i < 2; i++) {
            int u = t + 512 * i;
            int r = u >> 3, q = u & 7;
            unsigned off = sw128((unsigned)(r * 128 + q * 16));
            int row = nb + r;
            if (row < N) {
                cpa16(A_HI + off, g_x_hi + (size_t)row * 256 + c * 64 + q * 8);
                cpa16(A_LO + off, g_x_lo + (size_t)row * 256 + c * 64 + q * 8);
            } else {
                zfill16(A_HI + off);
                zfill16(A_LO + off);
            }
        }
#pragma unroll
        for (int i = 0; i < 4; i++) {
            int u = t + 512 * i;
            int n = u >> 3, q = u & 7;
            unsigned off = sw128((unsigned)(n * 128 + q * 16));
            cpa16(B_HI + off, Wh + (size_t)n * 256 + c * 64 + q * 8);
            cpa16(B_LO + off, Wl + (size_t)n * 256 + c * 64 + q * 8);
        }
        asm volatile("cp.async.commit_group;" ::: "memory");
        asm volatile("cp.async.wait_group 0;" ::: "memory");
        __syncthreads();

#pragma unroll
        for (int ks = 0; ks < 4; ks++) {
            unsigned ah[2][4], al[2][4];
#pragma unroll
            for (int mt = 0; mt < 2; mt++) {
                unsigned off = sw128((unsigned)((m0 + mt * 16 + (lane & 15)) * 128
                                                + ks * 32 + (lane >> 4) * 16));
                ldm_x4(ah[mt], A_HI + off);
                ldm_x4(al[mt], A_LO + off);
            }
#pragma unroll
            for (int nt = 0; nt < 4; nt++) {
                unsigned off = sw128((unsigned)((n0 + nt * 16 + (lane & 7)
                                                 + ((lane >> 4) & 1) * 8) * 128
                                                + ks * 32 + ((lane >> 3) & 1) * 16));
                unsigned bh[4], bl[4];
                ldm_x4(bh, B_HI + off);
                ldm_x4(bl, B_LO + off);
#pragma unroll
                for (int j = 0; j < 2; j++) {
                    int nn = nt * 2 + j;
#pragma unroll
                    for (int mt = 0; mt < 2; mt++) {
                        mma16816(acc[mt][nn], ah[mt], bh[2 * j], bh[2 * j + 1]);
                        mma16816(acc[mt][nn], ah[mt], bl[2 * j], bl[2 * j + 1]);
                        mma16816(acc[mt][nn], al[mt], bh[2 * j], bh[2 * j + 1]);
                    }
                }
            }
        }
    }

#pragma unroll
    for (int mt = 0; mt < 2; mt++) {
        int r0 = nb + m0 + mt * 16 + (lane >> 2);
        int r1 = r0 + 8;
#pragma unroll
        for (int nn = 0; nn < 8; nn++) {
            int col = n0 + nn * 8 + (lane & 3) * 2;
            if (r0 < N) {
                og[(size_t)r0 * WDIM + col]     = acc[mt][nn][0];
                og[(size_t)r0 * WDIM + col + 1] = acc[mt][nn][1];
            }
            if (r1 < N) {
                og[(size_t)r1 * WDIM + col]     = acc[mt][nn][2];
                og[(size_t)r1 * WDIM + col + 1] = acc[mt][nn][3];
            }
        }
    }
}

// ---------------------------------------------------------------------------
// K2 (fused), R17 = R16 + register diet targeting 3 CTAs/SM (84 regs).
// P1 in-place (xx->xn, bag->gn); P2 split into gate pass then val pass.
// smem 25600 B, 256 thr.
// ---------------------------------------------------------------------------
#define XNH_O  1024u
#define XNL_O  5120u
#define GINH_O 9216u
#define GINL_O 13312u
#define ACTH_O 17408u
#define ACTL_O 21504u

extern "C" __global__ void __launch_bounds__(256, 3)
fused_edge_kernel(const int* __restrict__ eidx, const int* __restrict__ eattr,
                  const float* __restrict__ emb, float* __restrict__ out, int E)
{
    extern __shared__ char smc[];
    unsigned sb = (unsigned)__cvta_generic_to_shared(smc);
    int* tgt_s = reinterpret_cast<int*>(smc);
    const int t = threadIdx.x, lane = t & 31, wid = t >> 5;
    const int eb = blockIdx.x * 32;

    if (t < 32) {
        int e = eb + t;
        tgt_s[t] = (e < E) ? __ldg(eidx + E + e) : -1;
    }
    __syncthreads();

    const int n0 = wid * 32;
    float acc[2][4][4];
#pragma unroll
    for (int mt = 0; mt < 2; mt++)
#pragma unroll
        for (int nn = 0; nn < 4; nn++)
#pragma unroll
            for (int q = 0; q < 4; q++) acc[mt][nn][q] = 0.f;

    const int e_l = t >> 3, sub = t & 7;
    const int e = eb + e_l;
    const int eg = wid >> 2, hl = (wid >> 1) & 1, nh = wid & 1;
    const int role = wid & 3;

#pragma unroll 1
    for (int c = 0; c < 4; c++) {
        // ---- P1: xn/gin for this chunk's 2 heads (in-place, low regs) ----
        {
            unsigned soff = sw128((unsigned)(e_l * 128 + sub * 16));
            if (e < E) {
                int s  = __ldg(eidx + e);
                int tg = tgt_s[e_l];
                const float4* ps = reinterpret_cast<const float4*>(
                    g_xs + (size_t)s * WDIM + c * 64 + sub * 8);
                const float4* pt = reinterpret_cast<const float4*>(
                    g_xt + (size_t)tg * WDIM + c * 64 + sub * 8);
                float xx[8];
                {
                    float4 a0 = ps[0], a1 = ps[1], b0 = pt[0], b1 = pt[1];
                    xx[0] = a0.x + b0.x; xx[1] = a0.y + b0.y; xx[2] = a0.z + b0.z; xx[3] = a0.w + b0.w;
                    xx[4] = a1.x + b1.x; xx[5] = a1.y + b1.y; xx[6] = a1.z + b1.z; xx[7] = a1.w + b1.w;
                }
                float sum = 0.f, sq = 0.f;
#pragma unroll
                for (int i = 0; i < 8; i++) { sum += xx[i]; sq += xx[i] * xx[i]; }
                sum += __shfl_xor_sync(0xFFFFFFFFu, sum, 1);
                sq  += __shfl_xor_sync(0xFFFFFFFFu, sq, 1);
                sum += __shfl_xor_sync(0xFFFFFFFFu, sum, 2);
                sq  += __shfl_xor_sync(0xFFFFFFFFu, sq, 2);
                float mu = sum * (1.f / 32.f);
                float var = sq * (1.f / 32.f) - mu * mu;
                float rstd = rsqrtf(var + 1e-5f);

                float bag[8];
#pragma unroll
                for (int i = 0; i < 8; i++) bag[i] = 0.f;
                float cnt = 0.f;
#pragma unroll
                for (int b = 0; b < 3; b++) {
                    int a = __ldg(eattr + (size_t)e * 3 + b);
                    if (a != 0) {
                        cnt += 1.f;
                        const float4* pe = reinterpret_cast<const float4*>(
                            emb + (size_t)a * WDIM + c * 64 + sub * 8);
                        float4 e0 = __ldg(pe), e1 = __ldg(pe + 1);
                        bag[0] += e0.x; bag[1] += e0.y; bag[2] += e0.z; bag[3] += e0.w;
                        bag[4] += e1.x; bag[5] += e1.y; bag[6] += e1.z; bag[7] += e1.w;
                    }
                }
                float inv = 1.f / fmaxf(cnt, 1.f);
                // in-place: xx becomes xn; bag becomes gn
#pragma unroll
                for (int i = 0; i < 8; i++) {
                    xx[i] = (xx[i] - mu) * rstd;
                    bag[i] = xx[i] + bag[i] * inv;
                }
                unsigned vh[4], vl[4];
#pragma unroll
                for (int p = 0; p < 4; p++) {
                    unsigned hp = bf2(xx[2 * p + 1], xx[2 * p]);
                    float h0 = __uint_as_float(hp << 16);
                    float h1 = __uint_as_float(hp & 0xFFFF0000u);
                    vh[p] = hp;
                    vl[p] = bf2(xx[2 * p + 1] - h1, xx[2 * p] - h0);
                }
                asm volatile("st.shared.v4.b32 [%0], {%1,%2,%3,%4};" ::
                             "r"(sb + XNH_O + soff), "r"(vh[0]), "r"(vh[1]), "r"(vh[2]), "r"(vh[3]));
                asm volatile("st.shared.v4.b32 [%0], {%1,%2,%3,%4};" ::
                             "r"(sb + XNL_O + soff), "r"(vl[0]), "r"(vl[1]), "r"(vl[2]), "r"(vl[3]));
#pragma unroll
                for (int p = 0; p < 4; p++) {
                    unsigned hp = bf2(bag[2 * p + 1], bag[2 * p]);
                    float h0 = __uint_as_float(hp << 16);
                    float h1 = __uint_as_float(hp & 0xFFFF0000u);
                    vh[p] = hp;
                    vl[p] = bf2(bag[2 * p + 1] - h1, bag[2 * p] - h0);
                }
                asm volatile("st.shared.v4.b32 [%0], {%1,%2,%3,%4};" ::
                             "r"(sb + GINH_O + soff), "r"(vh[0]), "r"(vh[1]), "r"(vh[2]), "r"(vh[3]));
                asm volatile("st.shared.v4.b32 [%0], {%1,%2,%3,%4};" ::
                             "r"(sb + GINL_O + soff), "r"(vl[0]), "r"(vl[1]), "r"(vl[2]), "r"(vl[3]));
            } else {
                asm volatile("st.shared.v4.b32 [%0], {%1,%1,%1,%1};" :: "r"(sb + XNH_O + soff), "r"(0u));
                asm volatile("st.shared.v4.b32 [%0], {%1,%1,%1,%1};" :: "r"(sb + XNL_O + soff), "r"(0u));
                asm volatile("st.shared.v4.b32 [%0], {%1,%1,%1,%1};" :: "r"(sb + GINH_O + soff), "r"(0u));
                asm volatile("st.shared.v4.b32 [%0], {%1,%1,%1,%1};" :: "r"(sb + GINL_O + soff), "r"(0u));
            }
        }
        __syncthreads();   // S1: xn/gin visible

        // ---- P2: gate pass then val pass (register reuse) ----
        {
            unsigned arow = (unsigned)((eg * 16 + (lane & 15)) * 128 + hl * 64 + (lane >> 4) * 16);
            const uint4* pw = reinterpret_cast<const uint4*>(
                g_wgv_frag + (size_t)(c * 4 + role) * 1024);
            float gacc[2][4], vacc[2][4];
#pragma unroll
            for (int j = 0; j < 2; j++)
#pragma unroll
                for (int q = 0; q < 4; q++) { gacc[j][q] = 0.f; vacc[j][q] = 0.f; }

            // gate pass: slots 0-15 (Wg hi, Wg lo)
            {
                unsigned bfr[16];
#pragma unroll
                for (int i = 0; i < 4; i++) {
                    uint4 q = __ldg(pw + i * 32 + lane);
                    bfr[i * 4] = q.x; bfr[i * 4 + 1] = q.y;
                    bfr[i * 4 + 2] = q.z; bfr[i * 4 + 3] = q.w;
                }
#pragma unroll
                for (int ks = 0; ks < 2; ks++) {
                    unsigned ah[4], al[4];
                    unsigned off = sw128(arow + ks * 32);
                    ldm_x4(ah, sb + GINH_O + off);
                    ldm_x4(al, sb + GINL_O + off);
#pragma unroll
                    for (int j = 0; j < 2; j++) {
                        mma16816(gacc[j], ah, bfr[ks * 4 + 2 * j],     bfr[ks * 4 + 2 * j + 1]);
                        mma16816(gacc[j], ah, bfr[8 + ks * 4 + 2 * j], bfr[8 + ks * 4 + 2 * j + 1]);
                        mma16816(gacc[j], al, bfr[ks * 4 + 2 * j],     bfr[ks * 4 + 2 * j + 1]);
                    }
                }
            }
            // val pass: slots 16-31 (Wv hi, Wv lo)
            {
                unsigned bfr[16];
#pragma unroll
                for (int i = 0; i < 4; i++) {
                    uint4 q = __ldg(pw + (i + 4) * 32 + lane);
                    bfr[i * 4] = q.x; bfr[i * 4 + 1] = q.y;
                    bfr[i * 4 + 2] = q.z; bfr[i * 4 + 3] = q.w;
                }
#pragma unroll
                for (int ks = 0; ks < 2; ks++) {
                    unsigned ah[4], al[4];
                    unsigned off = sw128(arow + ks * 32);
                    ldm_x4(ah, sb + XNH_O + off);
                    ldm_x4(al, sb + XNL_O + off);
#pragma unroll
                    for (int j = 0; j < 2; j++) {
                        mma16816(vacc[j], ah, bfr[ks * 4 + 2 * j],     bfr[ks * 4 + 2 * j + 1]);
                        mma16816(vacc[j], ah, bfr[8 + ks * 4 + 2 * j], bfr[8 + ks * 4 + 2 * j + 1]);
                        mma16816(vacc[j], al, bfr[ks * 4 + 2 * j],     bfr[ks * 4 + 2 * j + 1]);
                    }
                }
            }
#pragma unroll
            for (int j = 0; j < 2; j++)
#pragma unroll
                for (int half = 0; half < 2; half++) {
                    float a0 = fmaxf(gacc[j][half * 2], 0.f) * vacc[j][half * 2];
                    float a1 = fmaxf(gacc[j][half * 2 + 1], 0.f) * vacc[j][half * 2 + 1];
                    int row = eg * 16 + (lane >> 2) + half * 8;
                    int col = hl * 32 + nh * 16 + j * 8 + (lane & 3) * 2;
                    unsigned off = sw128((unsigned)(row * 128 + col * 2));
                    unsigned hp = bf2(a1, a0);
                    float h0 = __uint_as_float(hp << 16);
                    float h1 = __uint_as_float(hp & 0xFFFF0000u);
                    unsigned lp = bf2(a1 - h1, a0 - h0);
                    asm volatile("st.shared.b32 [%0], %1;" :: "r"(sb + ACTH_O + off), "r"(hp));
                    asm volatile("st.shared.b32 [%0], %1;" :: "r"(sb + ACTL_O + off), "r"(lp));
                }
        }
        __syncthreads();   // S2: act visible

        // ---- P3: W_post mainloop, WP fragments via coalesced LDG ----
        {
            const uint4* pwh = reinterpret_cast<const uint4*>(g_wpf_hi);
            const uint4* pwl = reinterpret_cast<const uint4*>(g_wpf_lo);
#pragma unroll
            for (int ks = 0; ks < 4; ks++) {
                unsigned ah[2][4], al[2][4];
#pragma unroll
                for (int mt = 0; mt < 2; mt++) {
                    unsigned off = sw128((unsigned)((mt * 16 + (lane & 15)) * 128
                                                    + ks * 32 + (lane >> 4) * 16));
                    ldm_x4(ah[mt], sb + ACTH_O + off);
                    ldm_x4(al[mt], sb + ACTL_O + off);
                }
#pragma unroll
                for (int nt = 0; nt < 2; nt++) {
                    unsigned idx = (unsigned)((((c * 4 + ks) * 8 + wid) * 2 + nt) * 32 + lane);
                    uint4 qh = __ldg(pwh + idx);
                    uint4 ql = __ldg(pwl + idx);
                    unsigned bh[4] = {qh.x, qh.y, qh.z, qh.w};
                    unsigned bl[4] = {ql.x, ql.y, ql.z, ql.w};
#pragma unroll
                    for (int j = 0; j < 2; j++) {
                        int nn = nt * 2 + j;
#pragma unroll
                        for (int mt = 0; mt < 2; mt++) {
                            mma16816(acc[mt][nn], ah[mt], bh[2 * j], bh[2 * j + 1]);
                            mma16816(acc[mt][nn], ah[mt], bl[2 * j], bl[2 * j + 1]);
                            mma16816(acc[mt][nn], al[mt], bh[2 * j], bh[2 * j + 1]);
                        }
                    }
                }
            }
        }
        // no chunk-end barrier (act(c+1) written only after S1(c+1))
    }

    // ---- epilogue: scatter ----
#pragma unroll
    for (int mt = 0; mt < 2; mt++) {
        int r0 = mt * 16 + (lane >> 2);
        int r1 = r0 + 8;
        int tg0 = tgt_s[r0], tg1 = tgt_s[r1];
        float* p0 = out + (size_t)(tg0 < 0 ? 0 : tg0) * WDIM;
        float* p1 = out + (size_t)(tg1 < 0 ? 0 : tg1) * WDIM;
#pragma unroll
        for (int nn = 0; nn < 4; nn++) {
            int col = n0 + nn * 8 + (lane & 3) * 2;
            if (tg0 >= 0)
                asm volatile("red.global.add.v2.f32 [%0], {%1,%2};" ::
                             "l"(p0 + col), "f"(acc[mt][nn][0]), "f"(acc[mt][nn][1]) : "memory");
            if (tg1 >= 0)
                asm volatile("red.global.add.v2.f32 [%0], {%1,%2};" ::
                             "l"(p1 + col), "f"(acc[mt][nn][2]), "f"(acc[mt][nn][3]) : "memory");
        }
    }
}

// ---------------------------------------------------------------------------
// K3: out[n,j] *= deg[n]^deg_param[j]
// ---------------------------------------------------------------------------
extern "C" __global__ void scale_kernel(float* __restrict__ out,
                                        const float* __restrict__ deg,
                                        const float* __restrict__ dp, int N)
{
    int idx = blockIdx.x * blockDim.x + threadIdx.x;
    if (idx < N * WDIM) {
        int n = idx >> 8, j = idx & 255;
        out[idx] *= __powf(__ldg(deg + n), __ldg(dp + j));
    }
}

// ---------------------------------------------------------------------------
extern "C" void kernel_launch(void* const* d_in, const int* in_sizes, int n_in,
                              void* d_out, int out_size)
{
    const float* x    = (const float*)d_in[0];
    const float* deg  = (const float*)d_in[1];
    const int*   eidx = (const int*)d_in[2];
    const int*   eattr= (const int*)d_in[3];
    const float* Wsrc = (const float*)d_in[4];
    const float* Wtgt = (const float*)d_in[5];
    const float* emb  = (const float*)d_in[6];
    const float* Wg   = (const float*)d_in[7];
    const float* Wv   = (const float*)d_in[8];
    const float* Wp   = (const float*)d_in[9];
    const float* dp   = (const float*)d_in[10];
    float* out = (float*)d_out;

    int N = in_sizes[0] / WDIM;
    int E = in_sizes[2] / 2;
    int xtotal = in_sizes[0];

    const int NODE_SMEM  = 98304;
    const int FUSED_SMEM = 25600;

    cudaFuncSetAttribute(hmma_node_kernel,
                         cudaFuncAttributeMaxDynamicSharedMemorySize, NODE_SMEM);
    cudaFuncSetAttribute(fused_edge_kernel,
                         cudaFuncAttributeMaxDynamicSharedMemorySize, FUSED_SMEM);

    cudaMemsetAsync(d_out, 0, (size_t)out_size * sizeof(float));

    xsplit_kernel<<<(xtotal + 511) / 512, 512>>>(x, xtotal);
    wsplit_kernel<<<64, 1024>>>(Wp, Wsrc, Wtgt, Wg, Wv);
    dim3 ng((N + 127) / 128, 2);
    hmma_node_kernel<<<ng, 512, NODE_SMEM>>>(N);
    fused_edge_kernel<<<(E + 31) / 32, 256, FUSED_SMEM>>>(eidx, eattr, emb, out, E);
    scale_kernel<<<((size_t)N * WDIM + 511) / 512, 512>>>(out, deg, dp, N);
}